// round 1
// baseline (speedup 1.0000x reference)
#include <cuda_runtime.h>

#define THW     1024
#define DMODEL  512
#define NHEAD   8
#define DHEAD   64
#define BATCH   4
#define TROWS   (BATCH*THW)   // 4096
#define LNEPS   1e-5f

// ---------------- scratch (device globals: allocation-free) ----------------
__device__ float g_xn[(size_t)TROWS * DMODEL];                 // 8 MB
__device__ float g_q [(size_t)NHEAD * TROWS * DHEAD];          // 8 MB
__device__ float g_k [(size_t)NHEAD * TROWS * DHEAD];          // 8 MB
__device__ float g_v [(size_t)NHEAD * TROWS * DHEAD];          // 8 MB
__device__ float g_s [(size_t)NHEAD * BATCH * THW * THW];      // 134 MB
__device__ float g_o [(size_t)TROWS * DMODEL];                 // 8 MB

// ---------------- LayerNorm: one block per row of 512 ----------------
__global__ void ln_kernel(const float* __restrict__ x,
                          const float* __restrict__ gamma,
                          const float* __restrict__ beta) {
    int row = blockIdx.x;
    const float* xr = x + (size_t)row * DMODEL;
    int t = threadIdx.x;
    float v0 = xr[t];
    float v1 = xr[t + 256];

    __shared__ float red[8];

    // mean
    float s = v0 + v1;
    #pragma unroll
    for (int o = 16; o; o >>= 1) s += __shfl_xor_sync(0xffffffffu, s, o);
    if ((t & 31) == 0) red[t >> 5] = s;
    __syncthreads();
    if (t < 8) {
        float m = red[t];
        #pragma unroll
        for (int o = 4; o; o >>= 1) m += __shfl_xor_sync(0xffu, m, o);
        if (t == 0) red[0] = m;
    }
    __syncthreads();
    float mu = red[0] * (1.0f / DMODEL);
    __syncthreads();

    // variance
    float d0 = v0 - mu, d1 = v1 - mu;
    float s2 = d0 * d0 + d1 * d1;
    #pragma unroll
    for (int o = 16; o; o >>= 1) s2 += __shfl_xor_sync(0xffffffffu, s2, o);
    if ((t & 31) == 0) red[t >> 5] = s2;
    __syncthreads();
    if (t < 8) {
        float m = red[t];
        #pragma unroll
        for (int o = 4; o; o >>= 1) m += __shfl_xor_sync(0xffu, m, o);
        if (t == 0) red[0] = m;
    }
    __syncthreads();
    float rstd = rsqrtf(red[0] * (1.0f / DMODEL) + LNEPS);

    float* xo = g_xn + (size_t)row * DMODEL;
    xo[t]       = d0 * rstd * gamma[t]       + beta[t];
    xo[t + 256] = d1 * rstd * gamma[t + 256] + beta[t + 256];
}

// ---------------- 4x4 per-thread FMA step ----------------
__device__ __forceinline__ void fma4x4(float acc[4][4], float4 a, float4 b) {
    float av[4] = {a.x, a.y, a.z, a.w};
    float bv[4] = {b.x, b.y, b.z, b.w};
    #pragma unroll
    for (int i = 0; i < 4; i++)
        #pragma unroll
        for (int j = 0; j < 4; j++)
            acc[i][j] = fmaf(av[i], bv[j], acc[i][j]);
}

// ---------------- QKV: z = h*3 + {q,k,v}, C[4096x64] = xn[4096x512] * W[512x64] ----------------
__global__ void qkv_kernel(const float* __restrict__ wq,
                           const float* __restrict__ wk,
                           const float* __restrict__ wv) {
    __shared__ float As[16][68];
    __shared__ float Bs[16][68];
    int z = blockIdx.z;
    int h = z / 3, sel = z % 3;
    const float* W = (sel == 0 ? wq : sel == 1 ? wk : wv) + (size_t)h * DMODEL * DHEAD;
    float* C = (sel == 0 ? g_q : sel == 1 ? g_k : g_v) + (size_t)h * TROWS * DHEAD;

    int m0 = blockIdx.x * 64;
    int tid = threadIdx.x, tx = tid & 15, ty = tid >> 4;
    float acc[4][4] = {};

    for (int k0 = 0; k0 < DMODEL; k0 += 16) {
        #pragma unroll
        for (int i = 0; i < 4; i++) {
            int idx = tid + i * 256;
            int m = idx >> 4, k = idx & 15;
            As[k][m] = g_xn[(size_t)(m0 + m) * DMODEL + k0 + k];
        }
        #pragma unroll
        for (int i = 0; i < 4; i++) {
            int idx = tid + i * 256;
            int k = idx >> 6, n = idx & 63;
            Bs[k][n] = W[(size_t)(k0 + k) * DHEAD + n];
        }
        __syncthreads();
        #pragma unroll
        for (int k = 0; k < 16; k++) {
            float4 a = *(const float4*)&As[k][ty * 4];
            float4 b = *(const float4*)&Bs[k][tx * 4];
            fma4x4(acc, a, b);
        }
        __syncthreads();
    }
    #pragma unroll
    for (int i = 0; i < 4; i++) {
        int m = m0 + ty * 4 + i;
        float4 r = make_float4(acc[i][0], acc[i][1], acc[i][2], acc[i][3]);
        *(float4*)&C[(size_t)m * DHEAD + tx * 4] = r;
    }
}

// ---------------- Scores: S = Q K^T / 8 + B, masked set to -1e4; z = h*4+b ----------------
__global__ void scores_kernel(const float* __restrict__ Bb, const int* __restrict__ Mm) {
    __shared__ float Qs[16][68];
    __shared__ float Ks[16][68];
    int z = blockIdx.z;
    const float* Q  = g_q + (size_t)z * THW * DHEAD;
    const float* Kp = g_k + (size_t)z * THW * DHEAD;
    float* S        = g_s + (size_t)z * THW * THW;
    const float* Bz = Bb  + (size_t)z * THW * THW;

    int q0 = blockIdx.y * 64, c0 = blockIdx.x * 64;
    int tid = threadIdx.x, tx = tid & 15, ty = tid >> 4;
    float acc[4][4] = {};

    for (int k0 = 0; k0 < DHEAD; k0 += 16) {
        #pragma unroll
        for (int i = 0; i < 4; i++) {
            int idx = tid + i * 256;
            int m = idx >> 4, k = idx & 15;
            Qs[k][m] = Q [(size_t)(q0 + m) * DHEAD + k0 + k];
            Ks[k][m] = Kp[(size_t)(c0 + m) * DHEAD + k0 + k];
        }
        __syncthreads();
        #pragma unroll
        for (int k = 0; k < 16; k++) {
            float4 a = *(const float4*)&Qs[k][ty * 4];
            float4 b = *(const float4*)&Ks[k][tx * 4];
            fma4x4(acc, a, b);
        }
        __syncthreads();
    }
    #pragma unroll
    for (int i = 0; i < 4; i++) {
        int q = q0 + ty * 4 + i;
        size_t off = (size_t)q * THW + c0 + tx * 4;
        float4 bb = *(const float4*)(Bz + off);
        int4   mm = *(const int4*)(Mm + off);
        float4 r;
        r.x = mm.x ? -10000.0f : fmaf(acc[i][0], 0.125f, bb.x);
        r.y = mm.y ? -10000.0f : fmaf(acc[i][1], 0.125f, bb.y);
        r.z = mm.z ? -10000.0f : fmaf(acc[i][2], 0.125f, bb.z);
        r.w = mm.w ? -10000.0f : fmaf(acc[i][3], 0.125f, bb.w);
        *(float4*)(S + off) = r;
    }
}

// ---------------- Row softmax over 1024, in place on g_s ----------------
__global__ void softmax_kernel() {
    size_t row = blockIdx.x;
    float* S = g_s + row * THW;
    int t = threadIdx.x;
    float4 v = ((float4*)S)[t];

    __shared__ float red[8];
    float mx = fmaxf(fmaxf(v.x, v.y), fmaxf(v.z, v.w));
    #pragma unroll
    for (int o = 16; o; o >>= 1) mx = fmaxf(mx, __shfl_xor_sync(0xffffffffu, mx, o));
    if ((t & 31) == 0) red[t >> 5] = mx;
    __syncthreads();
    if (t < 8) {
        float m = red[t];
        #pragma unroll
        for (int o = 4; o; o >>= 1) m = fmaxf(m, __shfl_xor_sync(0xffu, m, o));
        if (t == 0) red[0] = m;
    }
    __syncthreads();
    mx = red[0];
    __syncthreads();

    float e0 = expf(v.x - mx), e1 = expf(v.y - mx);
    float e2 = expf(v.z - mx), e3 = expf(v.w - mx);
    float s = e0 + e1 + e2 + e3;
    #pragma unroll
    for (int o = 16; o; o >>= 1) s += __shfl_xor_sync(0xffffffffu, s, o);
    if ((t & 31) == 0) red[t >> 5] = s;
    __syncthreads();
    if (t < 8) {
        float m = red[t];
        #pragma unroll
        for (int o = 4; o; o >>= 1) m += __shfl_xor_sync(0xffu, m, o);
        if (t == 0) red[0] = m;
    }
    __syncthreads();
    float inv = 1.0f / red[0];
    float4 r = make_float4(e0 * inv, e1 * inv, e2 * inv, e3 * inv);
    ((float4*)S)[t] = r;
}

// ---------------- PV: O[1024x64] = P[1024x1024] * V[1024x64]; write concat layout ----------------
__global__ void pv_kernel() {
    __shared__ float Ps[16][68];
    __shared__ float Vs[16][68];
    int z = blockIdx.z;
    int h = z >> 2, b = z & 3;
    const float* P = g_s + (size_t)z * THW * THW;
    const float* V = g_v + (size_t)z * THW * DHEAD;

    int m0 = blockIdx.x * 64;
    int tid = threadIdx.x, tx = tid & 15, ty = tid >> 4;
    float acc[4][4] = {};

    for (int k0 = 0; k0 < THW; k0 += 16) {
        #pragma unroll
        for (int i = 0; i < 4; i++) {
            int idx = tid + i * 256;
            int m = idx >> 4, k = idx & 15;
            Ps[k][m] = P[(size_t)(m0 + m) * THW + k0 + k];
        }
        #pragma unroll
        for (int i = 0; i < 4; i++) {
            int idx = tid + i * 256;
            int k = idx >> 6, n = idx & 63;
            Vs[k][n] = V[(size_t)(k0 + k) * DHEAD + n];
        }
        __syncthreads();
        #pragma unroll
        for (int k = 0; k < 16; k++) {
            float4 a = *(const float4*)&Ps[k][ty * 4];
            float4 b = *(const float4*)&Vs[k][tx * 4];
            fma4x4(acc, a, b);
        }
        __syncthreads();
    }
    #pragma unroll
    for (int i = 0; i < 4; i++) {
        int m = m0 + ty * 4 + i;
        float4 r = make_float4(acc[i][0], acc[i][1], acc[i][2], acc[i][3]);
        *(float4*)&g_o[(size_t)(b * THW + m) * DMODEL + h * DHEAD + tx * 4] = r;
    }
}

// ---------------- Proj: out = g_o[4096x512] @ wp^T + x ----------------
__global__ void proj_kernel(const float* __restrict__ x,
                            const float* __restrict__ wp,
                            float* __restrict__ out) {
    __shared__ float As[16][68];
    __shared__ float Bs[16][68];
    int m0 = blockIdx.y * 64, n0 = blockIdx.x * 64;
    int tid = threadIdx.x, tx = tid & 15, ty = tid >> 4;
    float acc[4][4] = {};

    for (int k0 = 0; k0 < DMODEL; k0 += 16) {
        #pragma unroll
        for (int i = 0; i < 4; i++) {
            int idx = tid + i * 256;
            int m = idx >> 4, k = idx & 15;
            As[k][m] = g_o[(size_t)(m0 + m) * DMODEL + k0 + k];
            // transposed weight load: Bs[k][n] = wp[n][k]
            Bs[k][m] = wp[(size_t)(n0 + m) * DMODEL + k0 + k];
        }
        __syncthreads();
        #pragma unroll
        for (int k = 0; k < 16; k++) {
            float4 a = *(const float4*)&As[k][ty * 4];
            float4 b = *(const float4*)&Bs[k][tx * 4];
            fma4x4(acc, a, b);
        }
        __syncthreads();
    }
    #pragma unroll
    for (int i = 0; i < 4; i++) {
        int m = m0 + ty * 4 + i;
        size_t off = (size_t)m * DMODEL + n0 + tx * 4;
        float4 xr = *(const float4*)(x + off);
        float4 r = make_float4(acc[i][0] + xr.x, acc[i][1] + xr.y,
                               acc[i][2] + xr.z, acc[i][3] + xr.w);
        *(float4*)(out + off) = r;
    }
}

// ---------------- launch ----------------
extern "C" void kernel_launch(void* const* d_in, const int* in_sizes, int n_in,
                              void* d_out, int out_size) {
    const float* x     = (const float*)d_in[0];
    const float* Bb    = (const float*)d_in[1];
    const int*   Mm    = (const int*)  d_in[2];
    const float* gamma = (const float*)d_in[3];
    const float* beta  = (const float*)d_in[4];
    const float* wq    = (const float*)d_in[5];
    const float* wk    = (const float*)d_in[6];
    const float* wv    = (const float*)d_in[7];
    const float* wp    = (const float*)d_in[8];
    float* out = (float*)d_out;

    ln_kernel<<<TROWS, 256>>>(x, gamma, beta);
    qkv_kernel<<<dim3(TROWS / 64, 1, NHEAD * 3), 256>>>(wq, wk, wv);
    scores_kernel<<<dim3(THW / 64, THW / 64, NHEAD * BATCH), 256>>>(Bb, Mm);
    softmax_kernel<<<NHEAD * BATCH * THW, 256>>>();
    pv_kernel<<<dim3(THW / 64, 1, NHEAD * BATCH), 256>>>();
    proj_kernel<<<dim3(DMODEL / 64, TROWS / 64), 256>>>(x, wp, out);
}

// round 3
// speedup vs baseline: 1.8934x; 1.8934x over previous
#include <cuda_runtime.h>
#include <cstdint>

#define THW 1024
#define DM  512
#define NH  8
#define DH  64
#define BS  4
#define TR  (BS*THW)       // 4096
#define LNEPS 1e-5f

// ---------------- scratch ----------------
__device__ float g_xn [(size_t)TR * DM];        // LN output (tf32-rounded)
__device__ float g_qkv[(size_t)TR * 1536];      // [row][ q(512) | k(512) | v(512) ] tf32
__device__ float g_o  [(size_t)TR * DM];        // concat attn out (tf32-rounded)
__device__ float g_wb [1536 * 512];             // QKV B operand [n][k], tf32
__device__ float g_wpr[512 * 512];              // wp [n][k], tf32

// ---------------- helpers ----------------
__device__ __forceinline__ float rna_tf32(float v) {
    uint32_t u;
    asm("cvt.rna.tf32.f32 %0, %1;" : "=r"(u) : "f"(v));
    return __uint_as_float(u);
}

// D += A(16x8,row) * B(8x8,col)  tf32
__device__ __forceinline__ void mma_tf32(float d[4], const uint32_t a[4], const uint32_t b[2]) {
    asm volatile(
        "mma.sync.aligned.m16n8k8.row.col.f32.tf32.tf32.f32 "
        "{%0,%1,%2,%3}, {%4,%5,%6,%7}, {%8,%9}, {%0,%1,%2,%3};"
        : "+f"(d[0]), "+f"(d[1]), "+f"(d[2]), "+f"(d[3])
        : "r"(a[0]), "r"(a[1]), "r"(a[2]), "r"(a[3]), "r"(b[0]), "r"(b[1]));
}

// ---------------- LayerNorm (writes tf32-rounded xn) ----------------
__global__ void ln_kernel(const float* __restrict__ x,
                          const float* __restrict__ gamma,
                          const float* __restrict__ beta) {
    int row = blockIdx.x;
    const float* xr = x + (size_t)row * DM;
    int t = threadIdx.x;
    float v0 = xr[t], v1 = xr[t + 256];

    __shared__ float red[8];
    float s = v0 + v1;
    #pragma unroll
    for (int o = 16; o; o >>= 1) s += __shfl_xor_sync(0xffffffffu, s, o);
    if ((t & 31) == 0) red[t >> 5] = s;
    __syncthreads();
    if (t < 8) {
        float m = red[t];
        #pragma unroll
        for (int o = 4; o; o >>= 1) m += __shfl_xor_sync(0xffu, m, o);
        if (t == 0) red[0] = m;
    }
    __syncthreads();
    float mu = red[0] * (1.0f / DM);
    __syncthreads();

    float d0 = v0 - mu, d1 = v1 - mu;
    float s2 = d0 * d0 + d1 * d1;
    #pragma unroll
    for (int o = 16; o; o >>= 1) s2 += __shfl_xor_sync(0xffffffffu, s2, o);
    if ((t & 31) == 0) red[t >> 5] = s2;
    __syncthreads();
    if (t < 8) {
        float m = red[t];
        #pragma unroll
        for (int o = 4; o; o >>= 1) m += __shfl_xor_sync(0xffu, m, o);
        if (t == 0) red[0] = m;
    }
    __syncthreads();
    float rstd = rsqrtf(red[0] * (1.0f / DM) + LNEPS);

    float* xo = g_xn + (size_t)row * DM;
    xo[t]       = rna_tf32(d0 * rstd * gamma[t]       + beta[t]);
    xo[t + 256] = rna_tf32(d1 * rstd * gamma[t + 256] + beta[t + 256]);
}

// ---------------- prep: pack weights into tf32 B operands ----------------
__global__ void prep_w(const float* __restrict__ wq, const float* __restrict__ wk,
                       const float* __restrict__ wv, const float* __restrict__ wp) {
    size_t idx = (size_t)blockIdx.x * 256 + threadIdx.x;
    if (idx < (size_t)1536 * 512) {
        int n = (int)(idx >> 9), k = (int)(idx & 511);
        int sel = n >> 9;
        int he = n & 511;
        int h = he >> 6, e = he & 63;
        const float* w = sel == 0 ? wq : sel == 1 ? wk : wv;
        g_wb[idx] = rna_tf32(w[((size_t)h * 512 + k) * 64 + e]);
    } else {
        size_t i2 = idx - (size_t)1536 * 512;
        if (i2 < (size_t)512 * 512) g_wpr[i2] = rna_tf32(wp[i2]);
    }
}

// ---------------- tf32 MMA GEMM: C[MxN] = A[MxK] * B[NxK]^T (+res, ?round) ----------------
#define PK 36
__global__ __launch_bounds__(256) void gemm_mma(const float* __restrict__ A,
                                                const float* __restrict__ Bw,
                                                float* __restrict__ C,
                                                const float* __restrict__ res,
                                                int K, int ldc, int round_out) {
    __shared__ float As[128 * PK];
    __shared__ float Bs[128 * PK];

    int tid = threadIdx.x, lane = tid & 31, warp = tid >> 5;
    int wm = (warp >> 2) * 64;     // 0 or 64
    int wn = (warp & 3) * 32;      // 0,32,64,96
    int m0 = blockIdx.x * 128, n0 = blockIdx.y * 128;

    float acc[4][4][4] = {};       // [mtile][ntile][reg]
    int g = lane >> 2, t4 = lane & 3;

    int NK = K >> 5;
    for (int kt = 0; kt < NK; kt++) {
        const float* Ag = A  + (size_t)m0 * K + kt * 32;
        const float* Bg = Bw + (size_t)n0 * K + kt * 32;
        #pragma unroll
        for (int i = 0; i < 4; i++) {
            int idx = tid + i * 256;           // 0..1023 float4 slots
            int r = idx >> 3, c4 = (idx & 7) * 4;
            *(float4*)&As[r * PK + c4] = *(const float4*)(Ag + (size_t)r * K + c4);
            *(float4*)&Bs[r * PK + c4] = *(const float4*)(Bg + (size_t)r * K + c4);
        }
        __syncthreads();
        #pragma unroll
        for (int ks = 0; ks < 4; ks++) {
            int k0 = ks * 8;
            uint32_t a[4][4], b[4][2];
            #pragma unroll
            for (int mt = 0; mt < 4; mt++) {
                int r = wm + mt * 16 + g;
                a[mt][0] = __float_as_uint(As[r * PK + k0 + t4]);
                a[mt][1] = __float_as_uint(As[(r + 8) * PK + k0 + t4]);
                a[mt][2] = __float_as_uint(As[r * PK + k0 + t4 + 4]);
                a[mt][3] = __float_as_uint(As[(r + 8) * PK + k0 + t4 + 4]);
            }
            #pragma unroll
            for (int nt = 0; nt < 4; nt++) {
                int n = wn + nt * 8 + g;
                b[nt][0] = __float_as_uint(Bs[n * PK + k0 + t4]);
                b[nt][1] = __float_as_uint(Bs[n * PK + k0 + t4 + 4]);
            }
            #pragma unroll
            for (int mt = 0; mt < 4; mt++)
                #pragma unroll
                for (int nt = 0; nt < 4; nt++)
                    mma_tf32(acc[mt][nt], a[mt], b[nt]);
        }
        __syncthreads();
    }

    // epilogue
    #pragma unroll
    for (int mt = 0; mt < 4; mt++) {
        #pragma unroll
        for (int nt = 0; nt < 4; nt++) {
            int r = m0 + wm + mt * 16 + g;
            int c = n0 + wn + nt * 8 + t4 * 2;
            float v0 = acc[mt][nt][0], v1 = acc[mt][nt][1];
            float v2 = acc[mt][nt][2], v3 = acc[mt][nt][3];
            size_t o0 = (size_t)r * ldc + c;
            size_t o1 = (size_t)(r + 8) * ldc + c;
            if (res) {
                float2 r0 = *(const float2*)(res + o0);
                float2 r1 = *(const float2*)(res + o1);
                v0 += r0.x; v1 += r0.y; v2 += r1.x; v3 += r1.y;
            }
            if (round_out) {
                v0 = rna_tf32(v0); v1 = rna_tf32(v1);
                v2 = rna_tf32(v2); v3 = rna_tf32(v3);
            }
            *(float2*)(C + o0) = make_float2(v0, v1);
            *(float2*)(C + o1) = make_float2(v2, v3);
        }
    }
}

// ---------------- fused flash attention with tf32 MMA ----------------
#define PKS 65   // Ks [e][c]
#define PVS 68   // Vs [c][e]
#define PPS 68   // Ps [q][c]
__global__ __launch_bounds__(128) void flash_kernel(const float* __restrict__ Bb,
                                                    const int* __restrict__ Mm) {
    extern __shared__ float smf[];
    float* Ks = smf;                     // [64][PKS]  (K transposed: [e][c])
    float* Vs = smf + 64 * PKS;          // [64][PVS]  ([c][e])
    float* Ps = smf + 64 * PKS + 64 * PVS; // [64][PPS] ([q][c])

    int z = blockIdx.z;
    int h = z >> 2, b = z & 3;
    int q0 = blockIdx.x * 64;
    int tid = threadIdx.x, lane = tid & 31, warp = tid >> 5;
    int g = lane >> 2, t4 = lane & 3;

    size_t rowbase = (size_t)b * THW;
    int qcol = h * 64, kcol = 512 + h * 64, vcol = 1024 + h * 64;

    // preload Q fragments (loop-invariant A operand): rows q0 + warp*16 + {g, g+8}
    uint32_t qa[8][4];
    {
        const float* Q0 = g_qkv + (rowbase + q0 + warp * 16 + g) * 1536 + qcol;
        const float* Q1 = Q0 + 8 * 1536;
        #pragma unroll
        for (int ks = 0; ks < 8; ks++) {
            int k = ks * 8 + t4;
            qa[ks][0] = __float_as_uint(Q0[k]);
            qa[ks][1] = __float_as_uint(Q1[k]);
            qa[ks][2] = __float_as_uint(Q0[k + 4]);
            qa[ks][3] = __float_as_uint(Q1[k + 4]);
        }
    }

    float oacc[8][4] = {};
    float rs0 = 0.f, rs1 = 0.f;
    const float* Bz = Bb + (size_t)z * THW * THW;
    int qr0 = q0 + warp * 16 + g;        // this thread's first q row (local)
    int qr1 = qr0 + 8;

    for (int c0 = 0; c0 < THW; c0 += 64) {
        __syncthreads();   // protect Ks/Vs (and Ps) reuse
        // load K (transposed) and V tiles
        #pragma unroll
        for (int i = 0; i < 8; i++) {
            int lin = tid + i * 128;         // 0..1023 float4 slots
            int nr = lin >> 4, k4 = (lin & 15) * 4;
            const float* rowp = g_qkv + (rowbase + c0 + nr) * 1536;
            float4 kv = *(const float4*)(rowp + kcol + k4);
            Ks[(k4 + 0) * PKS + nr] = kv.x;
            Ks[(k4 + 1) * PKS + nr] = kv.y;
            Ks[(k4 + 2) * PKS + nr] = kv.z;
            Ks[(k4 + 3) * PKS + nr] = kv.w;
            float4 vv = *(const float4*)(rowp + vcol + k4);
            *(float4*)&Vs[nr * PVS + k4] = vv;
        }
        __syncthreads();

        // S = Q K^T : 8 n-tiles of 8 cols, accumulate over 8 k-steps
        float sacc[8][4] = {};
        #pragma unroll
        for (int ks = 0; ks < 8; ks++) {
            int e = ks * 8 + t4;
            #pragma unroll
            for (int nt = 0; nt < 8; nt++) {
                uint32_t bfr[2];
                bfr[0] = __float_as_uint(Ks[e * PKS + nt * 8 + g]);
                bfr[1] = __float_as_uint(Ks[(e + 4) * PKS + nt * 8 + g]);
                mma_tf32(sacc[nt], qa[ks], bfr);
            }
        }

        // bias + mask + exp, write P to smem
        int prow = warp * 16 + g;
        #pragma unroll
        for (int nt = 0; nt < 8; nt++) {
            int cg = c0 + nt * 8 + t4 * 2;
            size_t bo0 = (size_t)qr0 * THW + cg;
            size_t bo1 = (size_t)qr1 * THW + cg;
            float2 b0 = *(const float2*)(Bz + bo0);
            float2 b1 = *(const float2*)(Bz + bo1);
            int2 m0v = *(const int2*)(Mm + bo0);
            int2 m1v = *(const int2*)(Mm + bo1);
            float p0 = m0v.x ? 0.f : __expf(fmaf(sacc[nt][0], 0.125f, b0.x));
            float p1 = m0v.y ? 0.f : __expf(fmaf(sacc[nt][1], 0.125f, b0.y));
            float p2 = m1v.x ? 0.f : __expf(fmaf(sacc[nt][2], 0.125f, b1.x));
            float p3 = m1v.y ? 0.f : __expf(fmaf(sacc[nt][3], 0.125f, b1.y));
            rs0 += p0 + p1;
            rs1 += p2 + p3;
            int pc = nt * 8 + t4 * 2;
            *(float2*)&Ps[prow * PPS + pc]       = make_float2(rna_tf32(p0), rna_tf32(p1));
            *(float2*)&Ps[(prow + 8) * PPS + pc] = make_float2(rna_tf32(p2), rna_tf32(p3));
        }
        __syncthreads();

        // O += P V : A = P (m=q, k=c), B = V (k=c, n=e)
        #pragma unroll
        for (int ks = 0; ks < 8; ks++) {
            int kc = ks * 8 + t4;
            uint32_t pa[4];
            pa[0] = __float_as_uint(Ps[prow * PPS + kc]);
            pa[1] = __float_as_uint(Ps[(prow + 8) * PPS + kc]);
            pa[2] = __float_as_uint(Ps[prow * PPS + kc + 4]);
            pa[3] = __float_as_uint(Ps[(prow + 8) * PPS + kc + 4]);
            #pragma unroll
            for (int nt = 0; nt < 8; nt++) {
                uint32_t bfr[2];
                bfr[0] = __float_as_uint(Vs[kc * PVS + nt * 8 + g]);
                bfr[1] = __float_as_uint(Vs[(kc + 4) * PVS + nt * 8 + g]);
                mma_tf32(oacc[nt], pa, bfr);
            }
        }
    }

    // row-sum reduction across the quad (lanes sharing g)
    rs0 += __shfl_xor_sync(0xffffffffu, rs0, 1);
    rs0 += __shfl_xor_sync(0xffffffffu, rs0, 2);
    rs1 += __shfl_xor_sync(0xffffffffu, rs1, 1);
    rs1 += __shfl_xor_sync(0xffffffffu, rs1, 2);
    float inv0 = 1.0f / rs0, inv1 = 1.0f / rs1;

    // store O (concat layout), tf32-rounded for proj GEMM
    #pragma unroll
    for (int nt = 0; nt < 8; nt++) {
        int cg = h * 64 + nt * 8 + t4 * 2;
        size_t o0 = (rowbase + qr0) * (size_t)DM + cg;
        size_t o1 = (rowbase + qr1) * (size_t)DM + cg;
        *(float2*)&g_o[o0] = make_float2(rna_tf32(oacc[nt][0] * inv0),
                                         rna_tf32(oacc[nt][1] * inv0));
        *(float2*)&g_o[o1] = make_float2(rna_tf32(oacc[nt][2] * inv1),
                                         rna_tf32(oacc[nt][3] * inv1));
    }
}

// ---------------- launch ----------------
extern "C" void kernel_launch(void* const* d_in, const int* in_sizes, int n_in,
                              void* d_out, int out_size) {
    const float* x     = (const float*)d_in[0];
    const float* Bb    = (const float*)d_in[1];
    const int*   Mm    = (const int*)  d_in[2];
    const float* gamma = (const float*)d_in[3];
    const float* beta  = (const float*)d_in[4];
    const float* wq    = (const float*)d_in[5];
    const float* wk    = (const float*)d_in[6];
    const float* wv    = (const float*)d_in[7];
    const float* wp    = (const float*)d_in[8];
    float* out = (float*)d_out;

    void *p_xn, *p_qkv, *p_o, *p_wb, *p_wpr;
    cudaGetSymbolAddress(&p_xn,  g_xn);
    cudaGetSymbolAddress(&p_qkv, g_qkv);
    cudaGetSymbolAddress(&p_o,   g_o);
    cudaGetSymbolAddress(&p_wb,  g_wb);
    cudaGetSymbolAddress(&p_wpr, g_wpr);

    const int flash_smem = (64 * PKS + 64 * PVS + 64 * PPS) * 4;  // 51456
    cudaFuncSetAttribute(flash_kernel, cudaFuncAttributeMaxDynamicSharedMemorySize, flash_smem);

    ln_kernel<<<TR, 256>>>(x, gamma, beta);
    prep_w<<<4096, 256>>>(wq, wk, wv, wp);
    // QKV: [4096x512] x [1536x512]^T -> g_qkv (tf32-rounded)
    gemm_mma<<<dim3(TR / 128, 1536 / 128), 256>>>(
        (const float*)p_xn, (const float*)p_wb, (float*)p_qkv, nullptr, 512, 1536, 1);
    // fused attention
    flash_kernel<<<dim3(THW / 64, 1, NH * BS), 128, flash_smem>>>(Bb, Mm);
    // proj + residual: [4096x512] x [512x512]^T + x -> out
    gemm_mma<<<dim3(TR / 128, DM / 128), 256>>>(
        (const float*)p_o, (const float*)p_wpr, out, x, 512, DM, 0);
}

// round 4
// speedup vs baseline: 2.6846x; 1.4178x over previous
#include <cuda_runtime.h>
#include <cstdint>

#define THW 1024
#define DM  512
#define NH  8
#define DH  64
#define BS  4
#define TR  (BS*THW)       // 4096
#define LNEPS 1e-5f

// ---------------- scratch ----------------
__device__ float g_xn [(size_t)TR * DM];
__device__ float g_qkv[(size_t)TR * 1536];      // [row][ q(512) | k(512) | v(512) ] tf32
__device__ float g_o  [(size_t)TR * DM];
__device__ float g_wb [1536 * 512];             // QKV B operand [n][k], tf32
__device__ float g_wpr[512 * 512];              // wp [n][k], tf32

// ---------------- helpers ----------------
__device__ __forceinline__ float rna_tf32(float v) {
    uint32_t u;
    asm("cvt.rna.tf32.f32 %0, %1;" : "=r"(u) : "f"(v));
    return __uint_as_float(u);
}
__device__ __forceinline__ uint32_t smem_u32(const void* p) {
    uint32_t a;
    asm("{ .reg .u64 t; cvta.to.shared.u64 t, %1; cvt.u32.u64 %0, t; }" : "=r"(a) : "l"(p));
    return a;
}
__device__ __forceinline__ void cp16(uint32_t dst, const void* src) {
    asm volatile("cp.async.cg.shared.global [%0], [%1], 16;" :: "r"(dst), "l"(src));
}
__device__ __forceinline__ void cp_commit() { asm volatile("cp.async.commit_group;"); }
__device__ __forceinline__ void cp_wait0()  { asm volatile("cp.async.wait_group 0;" ::: "memory"); }

// D += A(16x8,row) * B(8x8,col)  tf32
__device__ __forceinline__ void mma_tf32(float d[4], const uint32_t a[4], const uint32_t b[2]) {
    asm volatile(
        "mma.sync.aligned.m16n8k8.row.col.f32.tf32.tf32.f32 "
        "{%0,%1,%2,%3}, {%4,%5,%6,%7}, {%8,%9}, {%0,%1,%2,%3};"
        : "+f"(d[0]), "+f"(d[1]), "+f"(d[2]), "+f"(d[3])
        : "r"(a[0]), "r"(a[1]), "r"(a[2]), "r"(a[3]), "r"(b[0]), "r"(b[1]));
}

// ---------------- LayerNorm ----------------
__global__ void ln_kernel(const float* __restrict__ x,
                          const float* __restrict__ gamma,
                          const float* __restrict__ beta) {
    int row = blockIdx.x;
    const float* xr = x + (size_t)row * DM;
    int t = threadIdx.x;
    float v0 = xr[t], v1 = xr[t + 256];

    __shared__ float red[8];
    float s = v0 + v1;
    #pragma unroll
    for (int o = 16; o; o >>= 1) s += __shfl_xor_sync(0xffffffffu, s, o);
    if ((t & 31) == 0) red[t >> 5] = s;
    __syncthreads();
    if (t < 8) {
        float m = red[t];
        #pragma unroll
        for (int o = 4; o; o >>= 1) m += __shfl_xor_sync(0xffu, m, o);
        if (t == 0) red[0] = m;
    }
    __syncthreads();
    float mu = red[0] * (1.0f / DM);
    __syncthreads();

    float d0 = v0 - mu, d1 = v1 - mu;
    float s2 = d0 * d0 + d1 * d1;
    #pragma unroll
    for (int o = 16; o; o >>= 1) s2 += __shfl_xor_sync(0xffffffffu, s2, o);
    if ((t & 31) == 0) red[t >> 5] = s2;
    __syncthreads();
    if (t < 8) {
        float m = red[t];
        #pragma unroll
        for (int o = 4; o; o >>= 1) m += __shfl_xor_sync(0xffu, m, o);
        if (t == 0) red[0] = m;
    }
    __syncthreads();
    float rstd = rsqrtf(red[0] * (1.0f / DM) + LNEPS);

    float* xo = g_xn + (size_t)row * DM;
    xo[t]       = rna_tf32(d0 * rstd * gamma[t]       + beta[t]);
    xo[t + 256] = rna_tf32(d1 * rstd * gamma[t + 256] + beta[t + 256]);
}

// ---------------- prep: pack weights into tf32 B operands ----------------
__global__ void prep_w(const float* __restrict__ wq, const float* __restrict__ wk,
                       const float* __restrict__ wv, const float* __restrict__ wp) {
    size_t idx = (size_t)blockIdx.x * 256 + threadIdx.x;
    if (idx < (size_t)1536 * 512) {
        int n = (int)(idx >> 9), k = (int)(idx & 511);
        int sel = n >> 9;
        int he = n & 511;
        int h = he >> 6, e = he & 63;
        const float* w = sel == 0 ? wq : sel == 1 ? wk : wv;
        g_wb[idx] = rna_tf32(w[((size_t)h * 512 + k) * 64 + e]);
    } else {
        size_t i2 = idx - (size_t)1536 * 512;
        if (i2 < (size_t)512 * 512) g_wpr[i2] = rna_tf32(wp[i2]);
    }
}

// ---------------- tf32 MMA GEMM: C[MxN] = A[MxK] * B[NxK]^T (+res, ?round) ----------------
#define PK 36
__global__ __launch_bounds__(256) void gemm_mma(const float* __restrict__ A,
                                                const float* __restrict__ Bw,
                                                float* __restrict__ C,
                                                const float* __restrict__ res,
                                                int K, int ldc, int round_out) {
    __shared__ float As[128 * PK];
    __shared__ float Bs[128 * PK];
    uint32_t as_b = smem_u32(As), bs_b = smem_u32(Bs);

    int tid = threadIdx.x, lane = tid & 31, warp = tid >> 5;
    int wm = (warp >> 2) * 64;
    int wn = (warp & 3) * 32;
    int m0 = blockIdx.x * 128, n0 = blockIdx.y * 128;

    float acc[4][4][4] = {};
    int g = lane >> 2, t4 = lane & 3;

    int NK = K >> 5;
    for (int kt = 0; kt < NK; kt++) {
        const float* Ag = A  + (size_t)m0 * K + kt * 32;
        const float* Bg = Bw + (size_t)n0 * K + kt * 32;
        __syncthreads();
        #pragma unroll
        for (int i = 0; i < 4; i++) {
            int c = tid + i * 256;            // 0..1023 16B chunks
            int r = c >> 3, cc = c & 7;
            cp16(as_b + (uint32_t)(r * PK + cc * 4) * 4, Ag + (size_t)r * K + cc * 4);
            cp16(bs_b + (uint32_t)(r * PK + cc * 4) * 4, Bg + (size_t)r * K + cc * 4);
        }
        cp_commit();
        cp_wait0();
        __syncthreads();
        #pragma unroll
        for (int ks = 0; ks < 4; ks++) {
            int k0 = ks * 8;
            uint32_t a[4][4], b[4][2];
            #pragma unroll
            for (int mt = 0; mt < 4; mt++) {
                int r = wm + mt * 16 + g;
                a[mt][0] = __float_as_uint(As[r * PK + k0 + t4]);
                a[mt][1] = __float_as_uint(As[(r + 8) * PK + k0 + t4]);
                a[mt][2] = __float_as_uint(As[r * PK + k0 + t4 + 4]);
                a[mt][3] = __float_as_uint(As[(r + 8) * PK + k0 + t4 + 4]);
            }
            #pragma unroll
            for (int nt = 0; nt < 4; nt++) {
                int n = wn + nt * 8 + g;
                b[nt][0] = __float_as_uint(Bs[n * PK + k0 + t4]);
                b[nt][1] = __float_as_uint(Bs[n * PK + k0 + t4 + 4]);
            }
            #pragma unroll
            for (int mt = 0; mt < 4; mt++)
                #pragma unroll
                for (int nt = 0; nt < 4; nt++)
                    mma_tf32(acc[mt][nt], a[mt], b[nt]);
        }
    }

    #pragma unroll
    for (int mt = 0; mt < 4; mt++) {
        #pragma unroll
        for (int nt = 0; nt < 4; nt++) {
            int r = m0 + wm + mt * 16 + g;
            int c = n0 + wn + nt * 8 + t4 * 2;
            float v0 = acc[mt][nt][0], v1 = acc[mt][nt][1];
            float v2 = acc[mt][nt][2], v3 = acc[mt][nt][3];
            size_t o0 = (size_t)r * ldc + c;
            size_t o1 = (size_t)(r + 8) * ldc + c;
            if (res) {
                float2 r0 = *(const float2*)(res + o0);
                float2 r1 = *(const float2*)(res + o1);
                v0 += r0.x; v1 += r0.y; v2 += r1.x; v3 += r1.y;
            }
            if (round_out) {
                v0 = rna_tf32(v0); v1 = rna_tf32(v1);
                v2 = rna_tf32(v2); v3 = rna_tf32(v3);
            }
            *(float2*)(C + o0) = make_float2(v0, v1);
            *(float2*)(C + o1) = make_float2(v2, v3);
        }
    }
}

// ---------------- fused flash attention, tf32 MMA, P in registers ----------------
#define KPAD 68   // Ks [c][e] rows padded: banks 4g+t4 -> conflict-free
#define VPAD 72   // Vs [c][e] rows padded: banks 8t4+g -> conflict-free
__global__ __launch_bounds__(128, 4) void flash_kernel(const float* __restrict__ Bb,
                                                       const int* __restrict__ Mm) {
    extern __shared__ float smf[];
    float* Ks = smf;                 // [64][KPAD]
    float* Vs = smf + 64 * KPAD;     // [64][VPAD]
    uint32_t ks_b = smem_u32(Ks), vs_b = smem_u32(Vs);

    int z = blockIdx.z;
    int h = z >> 2, b = z & 3;
    int q0 = blockIdx.x * 64;
    int tid = threadIdx.x, lane = tid & 31, warp = tid >> 5;
    int g = lane >> 2, t4 = lane & 3;

    size_t rowbase = (size_t)b * THW;
    int qcol = h * 64, kcol = 512 + h * 64, vcol = 1024 + h * 64;

    // loop-invariant Q fragments: rows q0 + warp*16 + {g, g+8}
    uint32_t qa[8][4];
    {
        const float* Q0 = g_qkv + (rowbase + q0 + warp * 16 + g) * 1536 + qcol;
        const float* Q1 = Q0 + 8 * 1536;
        #pragma unroll
        for (int ks = 0; ks < 8; ks++) {
            int k = ks * 8 + t4;
            qa[ks][0] = __float_as_uint(Q0[k]);
            qa[ks][1] = __float_as_uint(Q1[k]);
            qa[ks][2] = __float_as_uint(Q0[k + 4]);
            qa[ks][3] = __float_as_uint(Q1[k + 4]);
        }
    }

    float oacc[8][4] = {};
    float rs0 = 0.f, rs1 = 0.f;
    const float* Bz = Bb + (size_t)z * THW * THW;
    int qr0 = q0 + warp * 16 + g;
    int qr1 = qr0 + 8;
    int lsrcA = (lane & ~3) | (t4 >> 1);
    int lsrcB = lsrcA + 2;
    bool odd = (t4 & 1) != 0;

    for (int c0 = 0; c0 < THW; c0 += 64) {
        __syncthreads();   // all warps done reading previous tile
        #pragma unroll
        for (int i = 0; i < 8; i++) {
            int c = tid + i * 128;          // 0..1023 16B chunks
            int r = c >> 4, cc = c & 15;
            const float* rowp = g_qkv + (rowbase + c0 + r) * 1536;
            cp16(ks_b + (uint32_t)(r * KPAD + cc * 4) * 4, rowp + kcol + cc * 4);
            cp16(vs_b + (uint32_t)(r * VPAD + cc * 4) * 4, rowp + vcol + cc * 4);
        }
        cp_commit();

        // prefetch bias/mask for nt = 0 while cp.async is in flight
        size_t bo0 = (size_t)qr0 * THW + c0 + t4 * 2;
        size_t bo1 = (size_t)qr1 * THW + c0 + t4 * 2;
        float2 nb0 = *(const float2*)(Bz + bo0);
        float2 nb1 = *(const float2*)(Bz + bo1);
        int2   nm0 = *(const int2*)(Mm + bo0);
        int2   nm1 = *(const int2*)(Mm + bo1);

        cp_wait0();
        __syncthreads();

        #pragma unroll
        for (int nt = 0; nt < 8; nt++) {
            float2 cb0 = nb0, cb1 = nb1;
            int2   cm0 = nm0, cm1 = nm1;
            if (nt < 7) {
                size_t p0o = bo0 + (nt + 1) * 8;
                size_t p1o = bo1 + (nt + 1) * 8;
                nb0 = *(const float2*)(Bz + p0o);
                nb1 = *(const float2*)(Bz + p1o);
                nm0 = *(const int2*)(Mm + p0o);
                nm1 = *(const int2*)(Mm + p1o);
            }

            // S tile (16q x 8c): chained over 8 k-steps
            float sacc[4] = {};
            const float* krow = Ks + (nt * 8 + g) * KPAD;
            #pragma unroll
            for (int ks = 0; ks < 8; ks++) {
                uint32_t bfr[2];
                bfr[0] = __float_as_uint(krow[ks * 8 + t4]);
                bfr[1] = __float_as_uint(krow[ks * 8 + t4 + 4]);
                mma_tf32(sacc, qa[ks], bfr);
            }

            // bias + mask + exp (no-max softmax: masked -> exactly 0)
            float p0 = cm0.x ? 0.f : __expf(fmaf(sacc[0], 0.125f, cb0.x));
            float p1 = cm0.y ? 0.f : __expf(fmaf(sacc[1], 0.125f, cb0.y));
            float p2 = cm1.x ? 0.f : __expf(fmaf(sacc[2], 0.125f, cb1.x));
            float p3 = cm1.y ? 0.f : __expf(fmaf(sacc[3], 0.125f, cb1.y));
            rs0 += p0 + p1;
            rs1 += p2 + p3;
            p0 = rna_tf32(p0); p1 = rna_tf32(p1);
            p2 = rna_tf32(p2); p3 = rna_tf32(p3);

            // C-fragment -> A-fragment via quad shuffles
            float x0 = __shfl_sync(0xffffffffu, p0, lsrcA);
            float x1 = __shfl_sync(0xffffffffu, p1, lsrcA);
            float y0 = __shfl_sync(0xffffffffu, p2, lsrcA);
            float y1 = __shfl_sync(0xffffffffu, p3, lsrcA);
            float z0 = __shfl_sync(0xffffffffu, p0, lsrcB);
            float z1 = __shfl_sync(0xffffffffu, p1, lsrcB);
            float w0 = __shfl_sync(0xffffffffu, p2, lsrcB);
            float w1 = __shfl_sync(0xffffffffu, p3, lsrcB);
            uint32_t pa[4];
            pa[0] = __float_as_uint(odd ? x1 : x0);
            pa[1] = __float_as_uint(odd ? y1 : y0);
            pa[2] = __float_as_uint(odd ? z1 : z0);
            pa[3] = __float_as_uint(odd ? w1 : w0);

            // O += P(:, kg=nt) * V(kg, :)
            const float* vr0 = Vs + (nt * 8 + t4) * VPAD;
            const float* vr1 = vr0 + 4 * VPAD;
            #pragma unroll
            for (int ne = 0; ne < 8; ne++) {
                uint32_t bfr[2];
                bfr[0] = __float_as_uint(vr0[ne * 8 + g]);
                bfr[1] = __float_as_uint(vr1[ne * 8 + g]);
                mma_tf32(oacc[ne], pa, bfr);
            }
        }
    }

    // row-sum reduction across the quad
    rs0 += __shfl_xor_sync(0xffffffffu, rs0, 1);
    rs0 += __shfl_xor_sync(0xffffffffu, rs0, 2);
    rs1 += __shfl_xor_sync(0xffffffffu, rs1, 1);
    rs1 += __shfl_xor_sync(0xffffffffu, rs1, 2);
    float inv0 = 1.0f / rs0, inv1 = 1.0f / rs1;

    #pragma unroll
    for (int nt = 0; nt < 8; nt++) {
        int cg = h * 64 + nt * 8 + t4 * 2;
        size_t o0 = (rowbase + qr0) * (size_t)DM + cg;
        size_t o1 = (rowbase + qr1) * (size_t)DM + cg;
        *(float2*)&g_o[o0] = make_float2(rna_tf32(oacc[nt][0] * inv0),
                                         rna_tf32(oacc[nt][1] * inv0));
        *(float2*)&g_o[o1] = make_float2(rna_tf32(oacc[nt][2] * inv1),
                                         rna_tf32(oacc[nt][3] * inv1));
    }
}

// ---------------- launch ----------------
extern "C" void kernel_launch(void* const* d_in, const int* in_sizes, int n_in,
                              void* d_out, int out_size) {
    const float* x     = (const float*)d_in[0];
    const float* Bb    = (const float*)d_in[1];
    const int*   Mm    = (const int*)  d_in[2];
    const float* gamma = (const float*)d_in[3];
    const float* beta  = (const float*)d_in[4];
    const float* wq    = (const float*)d_in[5];
    const float* wk    = (const float*)d_in[6];
    const float* wv    = (const float*)d_in[7];
    const float* wp    = (const float*)d_in[8];
    float* out = (float*)d_out;

    void *p_xn, *p_qkv, *p_o, *p_wb, *p_wpr;
    cudaGetSymbolAddress(&p_xn,  g_xn);
    cudaGetSymbolAddress(&p_qkv, g_qkv);
    cudaGetSymbolAddress(&p_o,   g_o);
    cudaGetSymbolAddress(&p_wb,  g_wb);
    cudaGetSymbolAddress(&p_wpr, g_wpr);

    const int flash_smem = (64 * KPAD + 64 * VPAD) * 4;   // 35840
    cudaFuncSetAttribute(flash_kernel, cudaFuncAttributeMaxDynamicSharedMemorySize, flash_smem);

    ln_kernel<<<TR, 256>>>(x, gamma, beta);
    prep_w<<<4096, 256>>>(wq, wk, wv, wp);
    gemm_mma<<<dim3(TR / 128, 1536 / 128), 256>>>(
        (const float*)p_xn, (const float*)p_wb, (float*)p_qkv, nullptr, 512, 1536, 1);
    flash_kernel<<<dim3(THW / 64, 1, NH * BS), 128, flash_smem>>>(Bb, Mm);
    gemm_mma<<<dim3(TR / 128, DM / 128), 256>>>(
        (const float*)p_o, (const float*)p_wpr, out, x, 512, DM, 0);
}

// round 5
// speedup vs baseline: 3.1645x; 1.1788x over previous
#include <cuda_runtime.h>
#include <cstdint>

#define THW 1024
#define DM  512
#define NH  8
#define DH  64
#define BS  4
#define TR  (BS*THW)       // 4096
#define LNEPS 1e-5f

// ---------------- scratch ----------------
__device__ float    g_xn [(size_t)TR * DM];
__device__ float    g_qkv[(size_t)TR * 1536];      // [row][ q(512) | k(512) | v(512) ] tf32
__device__ float    g_o  [(size_t)TR * DM];
__device__ float    g_wb [1536 * 512];             // QKV B operand [n][k], tf32
__device__ float    g_wpr[512 * 512];              // wp [n][k], tf32
__device__ uint32_t g_vt [(size_t)32 * 64 * 512];  // packed bf16 V^T: [z][e][cp], cp = c/2

// ---------------- helpers ----------------
__device__ __forceinline__ float rna_tf32(float v) {
    uint32_t u;
    asm("cvt.rna.tf32.f32 %0, %1;" : "=r"(u) : "f"(v));
    return __uint_as_float(u);
}
__device__ __forceinline__ uint32_t pack_bf16(float lo, float hi) {
    uint32_t r;
    asm("cvt.rn.bf16x2.f32 %0, %1, %2;" : "=r"(r) : "f"(hi), "f"(lo));
    return r;
}
__device__ __forceinline__ uint32_t smem_u32(const void* p) {
    uint32_t a;
    asm("{ .reg .u64 t; cvta.to.shared.u64 t, %1; cvt.u32.u64 %0, t; }" : "=r"(a) : "l"(p));
    return a;
}
__device__ __forceinline__ void cp16(uint32_t dst, const void* src) {
    asm volatile("cp.async.cg.shared.global [%0], [%1], 16;" :: "r"(dst), "l"(src));
}
__device__ __forceinline__ void cp_commit() { asm volatile("cp.async.commit_group;"); }

// D += A(16x8,row,tf32) * B(8x8,col,tf32)
__device__ __forceinline__ void mma_tf32(float d[4], const uint32_t a[4], const uint32_t b[2]) {
    asm volatile(
        "mma.sync.aligned.m16n8k8.row.col.f32.tf32.tf32.f32 "
        "{%0,%1,%2,%3}, {%4,%5,%6,%7}, {%8,%9}, {%0,%1,%2,%3};"
        : "+f"(d[0]), "+f"(d[1]), "+f"(d[2]), "+f"(d[3])
        : "r"(a[0]), "r"(a[1]), "r"(a[2]), "r"(a[3]), "r"(b[0]), "r"(b[1]));
}
// D += A(16x16,row,bf16) * B(16x8,col,bf16)
__device__ __forceinline__ void mma_bf16(float d[4], const uint32_t a[4], const uint32_t b[2]) {
    asm volatile(
        "mma.sync.aligned.m16n8k16.row.col.f32.bf16.bf16.f32 "
        "{%0,%1,%2,%3}, {%4,%5,%6,%7}, {%8,%9}, {%0,%1,%2,%3};"
        : "+f"(d[0]), "+f"(d[1]), "+f"(d[2]), "+f"(d[3])
        : "r"(a[0]), "r"(a[1]), "r"(a[2]), "r"(a[3]), "r"(b[0]), "r"(b[1]));
}

// ---------------- LayerNorm ----------------
__global__ void ln_kernel(const float* __restrict__ x,
                          const float* __restrict__ gamma,
                          const float* __restrict__ beta) {
    int row = blockIdx.x;
    const float* xr = x + (size_t)row * DM;
    int t = threadIdx.x;
    float v0 = xr[t], v1 = xr[t + 256];

    __shared__ float red[8];
    float s = v0 + v1;
    #pragma unroll
    for (int o = 16; o; o >>= 1) s += __shfl_xor_sync(0xffffffffu, s, o);
    if ((t & 31) == 0) red[t >> 5] = s;
    __syncthreads();
    if (t < 8) {
        float m = red[t];
        #pragma unroll
        for (int o = 4; o; o >>= 1) m += __shfl_xor_sync(0xffu, m, o);
        if (t == 0) red[0] = m;
    }
    __syncthreads();
    float mu = red[0] * (1.0f / DM);
    __syncthreads();

    float d0 = v0 - mu, d1 = v1 - mu;
    float s2 = d0 * d0 + d1 * d1;
    #pragma unroll
    for (int o = 16; o; o >>= 1) s2 += __shfl_xor_sync(0xffffffffu, s2, o);
    if ((t & 31) == 0) red[t >> 5] = s2;
    __syncthreads();
    if (t < 8) {
        float m = red[t];
        #pragma unroll
        for (int o = 4; o; o >>= 1) m += __shfl_xor_sync(0xffu, m, o);
        if (t == 0) red[0] = m;
    }
    __syncthreads();
    float rstd = rsqrtf(red[0] * (1.0f / DM) + LNEPS);

    float* xo = g_xn + (size_t)row * DM;
    xo[t]       = rna_tf32(d0 * rstd * gamma[t]       + beta[t]);
    xo[t + 256] = rna_tf32(d1 * rstd * gamma[t + 256] + beta[t + 256]);
}

// ---------------- prep: pack weights into tf32 B operands ----------------
__global__ void prep_w(const float* __restrict__ wq, const float* __restrict__ wk,
                       const float* __restrict__ wv, const float* __restrict__ wp) {
    size_t idx = (size_t)blockIdx.x * 256 + threadIdx.x;
    if (idx < (size_t)1536 * 512) {
        int n = (int)(idx >> 9), k = (int)(idx & 511);
        int sel = n >> 9;
        int he = n & 511;
        int h = he >> 6, e = he & 63;
        const float* w = sel == 0 ? wq : sel == 1 ? wk : wv;
        g_wb[idx] = rna_tf32(w[((size_t)h * 512 + k) * 64 + e]);
    } else {
        size_t i2 = idx - (size_t)1536 * 512;
        if (i2 < (size_t)512 * 512) g_wpr[i2] = rna_tf32(wp[i2]);
    }
}

// ---------------- V repack: g_qkv v-section -> g_vt (bf16x2, [z][e][cp]) ----------------
__global__ __launch_bounds__(256) void vpack_kernel() {
    __shared__ float sm[64 * 68];
    int z = blockIdx.y, ct = blockIdx.x;
    int h = z >> 2, b = z & 3;
    int tid = threadIdx.x;
    const float* src = g_qkv + ((size_t)(b * THW + ct * 64)) * 1536 + 1024 + h * 64;
    #pragma unroll
    for (int i = 0; i < 4; i++) {
        int c4 = tid + i * 256;
        int r = c4 >> 4, e4 = c4 & 15;
        *(float4*)&sm[r * 68 + e4 * 4] = *(const float4*)(src + (size_t)r * 1536 + e4 * 4);
    }
    __syncthreads();
    #pragma unroll
    for (int i = 0; i < 2; i++) {
        int idx = tid + i * 256;          // 0..511
        int e = idx >> 3, cpg = idx & 7;
        uint4 out;
        uint32_t* po = (uint32_t*)&out;
        #pragma unroll
        for (int m = 0; m < 4; m++) {
            int cp = cpg * 4 + m;
            po[m] = pack_bf16(sm[(2 * cp) * 68 + e], sm[(2 * cp + 1) * 68 + e]);
        }
        *(uint4*)&g_vt[((size_t)(z * 64) + e) * 512 + ct * 32 + cpg * 4] = out;
    }
}

// ---------------- tf32 MMA GEMM, 2-stage cp.async pipeline ----------------
#define PK 36
#define GSTG (128 * PK * 2)   // floats per stage (As + Bs)
__global__ __launch_bounds__(256) void gemm_mma(const float* __restrict__ A,
                                                const float* __restrict__ Bw,
                                                float* __restrict__ C,
                                                const float* __restrict__ res,
                                                int K, int ldc, int round_out) {
    extern __shared__ float gsm[];
    int tid = threadIdx.x, lane = tid & 31, warp = tid >> 5;
    int wm = (warp >> 2) * 64;
    int wn = (warp & 3) * 32;
    int m0 = blockIdx.x * 128, n0 = blockIdx.y * 128;
    int g = lane >> 2, t4 = lane & 3;

    float acc[4][4][4] = {};
    int NK = K >> 5;

    auto fill = [&](int kt, int s) {
        const float* Ag = A  + (size_t)m0 * K + kt * 32;
        const float* Bg = Bw + (size_t)n0 * K + kt * 32;
        uint32_t ab = smem_u32(gsm + s * GSTG);
        uint32_t bb = ab + 128 * PK * 4;
        #pragma unroll
        for (int i = 0; i < 4; i++) {
            int c = tid + i * 256;
            int r = c >> 3, cc = c & 7;
            cp16(ab + (uint32_t)(r * PK + cc * 4) * 4, Ag + (size_t)r * K + cc * 4);
            cp16(bb + (uint32_t)(r * PK + cc * 4) * 4, Bg + (size_t)r * K + cc * 4);
        }
        cp_commit();
    };

    fill(0, 0);
    for (int kt = 0; kt < NK; kt++) {
        int st = kt & 1;
        if (kt + 1 < NK) {
            fill(kt + 1, st ^ 1);
            asm volatile("cp.async.wait_group 1;" ::: "memory");
        } else {
            asm volatile("cp.async.wait_group 0;" ::: "memory");
        }
        __syncthreads();
        const float* As = gsm + st * GSTG;
        const float* Bs = As + 128 * PK;
        #pragma unroll
        for (int ks = 0; ks < 4; ks++) {
            int k0 = ks * 8;
            uint32_t a[4][4], b[4][2];
            #pragma unroll
            for (int mt = 0; mt < 4; mt++) {
                int r = wm + mt * 16 + g;
                a[mt][0] = __float_as_uint(As[r * PK + k0 + t4]);
                a[mt][1] = __float_as_uint(As[(r + 8) * PK + k0 + t4]);
                a[mt][2] = __float_as_uint(As[r * PK + k0 + t4 + 4]);
                a[mt][3] = __float_as_uint(As[(r + 8) * PK + k0 + t4 + 4]);
            }
            #pragma unroll
            for (int nt = 0; nt < 4; nt++) {
                int n = wn + nt * 8 + g;
                b[nt][0] = __float_as_uint(Bs[n * PK + k0 + t4]);
                b[nt][1] = __float_as_uint(Bs[n * PK + k0 + t4 + 4]);
            }
            #pragma unroll
            for (int mt = 0; mt < 4; mt++)
                #pragma unroll
                for (int nt = 0; nt < 4; nt++)
                    mma_tf32(acc[mt][nt], a[mt], b[nt]);
        }
        __syncthreads();
    }

    #pragma unroll
    for (int mt = 0; mt < 4; mt++) {
        #pragma unroll
        for (int nt = 0; nt < 4; nt++) {
            int r = m0 + wm + mt * 16 + g;
            int c = n0 + wn + nt * 8 + t4 * 2;
            float v0 = acc[mt][nt][0], v1 = acc[mt][nt][1];
            float v2 = acc[mt][nt][2], v3 = acc[mt][nt][3];
            size_t o0 = (size_t)r * ldc + c;
            size_t o1 = (size_t)(r + 8) * ldc + c;
            if (res) {
                float2 r0 = *(const float2*)(res + o0);
                float2 r1 = *(const float2*)(res + o1);
                v0 += r0.x; v1 += r0.y; v2 += r1.x; v3 += r1.y;
            }
            if (round_out) {
                v0 = rna_tf32(v0); v1 = rna_tf32(v1);
                v2 = rna_tf32(v2); v3 = rna_tf32(v3);
            }
            *(float2*)(C + o0) = make_float2(v0, v1);
            *(float2*)(C + o1) = make_float2(v2, v3);
        }
    }
}

// ---------------- fused flash attention: tf32 QK^T, bf16 PV, 2-stage pipeline ----------------
#define KPAD 68                 // Ks [c][e] float, banks 4g+t4 conflict-free
#define VTS  36                 // Vst [e][cp] uint32, banks 4g+t4 conflict-free
#define FSTG_B (64 * KPAD * 4 + 64 * VTS * 4)   // 26624 bytes per stage
__global__ __launch_bounds__(128, 4) void flash_kernel(const float* __restrict__ Bb,
                                                       const int* __restrict__ Mm) {
    extern __shared__ float smf[];
    int z = blockIdx.z;
    int h = z >> 2, b = z & 3;
    int q0 = blockIdx.x * 64;
    int tid = threadIdx.x, lane = tid & 31, warp = tid >> 5;
    int g = lane >> 2, t4 = lane & 3;

    size_t rowbase = (size_t)b * THW;
    int kcol = 512 + h * 64;
    uint32_t smbase = smem_u32(smf);

    // loop-invariant Q fragments
    uint32_t qa[8][4];
    {
        const float* Q0 = g_qkv + (rowbase + q0 + warp * 16 + g) * 1536 + h * 64;
        const float* Q1 = Q0 + 8 * 1536;
        #pragma unroll
        for (int ks = 0; ks < 8; ks++) {
            int k = ks * 8 + t4;
            qa[ks][0] = __float_as_uint(Q0[k]);
            qa[ks][1] = __float_as_uint(Q1[k]);
            qa[ks][2] = __float_as_uint(Q0[k + 4]);
            qa[ks][3] = __float_as_uint(Q1[k + 4]);
        }
    }

    float oacc[8][4] = {};
    float rs0 = 0.f, rs1 = 0.f;
    const float* Bz = Bb + (size_t)z * THW * THW;
    int qr0 = q0 + warp * 16 + g;
    int qr1 = qr0 + 8;

    auto fill = [&](int it, int s) {
        int c0 = it * 64;
        uint32_t kb = smbase + s * FSTG_B;
        uint32_t vb = kb + 64 * KPAD * 4;
        #pragma unroll
        for (int i = 0; i < 8; i++) {
            int c = tid + i * 128;
            int r = c >> 4, cc = c & 15;
            cp16(kb + (uint32_t)(r * KPAD + cc * 4) * 4,
                 g_qkv + (rowbase + c0 + r) * 1536 + kcol + cc * 4);
        }
        #pragma unroll
        for (int i = 0; i < 4; i++) {
            int c = tid + i * 128;
            int e = c >> 3, jj = c & 7;
            cp16(vb + (uint32_t)(e * VTS + jj * 4) * 4,
                 &g_vt[((size_t)(z * 64) + e) * 512 + (c0 >> 1) + jj * 4]);
        }
        cp_commit();
    };

    fill(0, 0);
    for (int it = 0; it < 16; it++) {
        int st = it & 1;
        int c0 = it * 64;
        if (it < 15) {
            fill(it + 1, st ^ 1);
            asm volatile("cp.async.wait_group 1;" ::: "memory");
        } else {
            asm volatile("cp.async.wait_group 0;" ::: "memory");
        }
        __syncthreads();
        const float* Ks = smf + st * (FSTG_B / 4);
        const uint32_t* Vst = (const uint32_t*)(Ks + 64 * KPAD);

        #pragma unroll
        for (int j = 0; j < 4; j++) {
            // bias/mask (independent of MMA chain; compiler schedules early)
            int ca = c0 + j * 16 + t4 * 2;
            size_t bo0 = (size_t)qr0 * THW + ca;
            size_t bo1 = (size_t)qr1 * THW + ca;
            float2 bA0 = *(const float2*)(Bz + bo0);
            float2 bA1 = *(const float2*)(Bz + bo1);
            float2 bB0 = *(const float2*)(Bz + bo0 + 8);
            float2 bB1 = *(const float2*)(Bz + bo1 + 8);
            int2 mA0 = *(const int2*)(Mm + bo0);
            int2 mA1 = *(const int2*)(Mm + bo1);
            int2 mB0 = *(const int2*)(Mm + bo0 + 8);
            int2 mB1 = *(const int2*)(Mm + bo1 + 8);

            // two S 16x8 tiles (ntA=2j, ntB=2j+1), ILP-2 chains
            float saccA[4] = {}, saccB[4] = {};
            const float* krA = Ks + (j * 16 + g) * KPAD;
            const float* krB = krA + 8 * KPAD;
            #pragma unroll
            for (int ks = 0; ks < 8; ks++) {
                uint32_t fA[2], fB[2];
                fA[0] = __float_as_uint(krA[ks * 8 + t4]);
                fA[1] = __float_as_uint(krA[ks * 8 + t4 + 4]);
                fB[0] = __float_as_uint(krB[ks * 8 + t4]);
                fB[1] = __float_as_uint(krB[ks * 8 + t4 + 4]);
                mma_tf32(saccA, qa[ks], fA);
                mma_tf32(saccB, qa[ks], fB);
            }

            // bias + mask + exp (no-max softmax: masked -> exactly 0)
            float pA0 = mA0.x ? 0.f : __expf(fmaf(saccA[0], 0.125f, bA0.x));
            float pA1 = mA0.y ? 0.f : __expf(fmaf(saccA[1], 0.125f, bA0.y));
            float pA2 = mA1.x ? 0.f : __expf(fmaf(saccA[2], 0.125f, bA1.x));
            float pA3 = mA1.y ? 0.f : __expf(fmaf(saccA[3], 0.125f, bA1.y));
            float pB0 = mB0.x ? 0.f : __expf(fmaf(saccB[0], 0.125f, bB0.x));
            float pB1 = mB0.y ? 0.f : __expf(fmaf(saccB[1], 0.125f, bB0.y));
            float pB2 = mB1.x ? 0.f : __expf(fmaf(saccB[2], 0.125f, bB1.x));
            float pB3 = mB1.y ? 0.f : __expf(fmaf(saccB[3], 0.125f, bB1.y));
            rs0 += pA0 + pA1 + pB0 + pB1;
            rs1 += pA2 + pA3 + pB2 + pB3;

            // S C-frags -> bf16 A-frag (no shuffles)
            uint32_t pa[4];
            pa[0] = pack_bf16(pA0, pA1);
            pa[1] = pack_bf16(pA2, pA3);
            pa[2] = pack_bf16(pB0, pB1);
            pa[3] = pack_bf16(pB2, pB3);

            // O += P[:, j*16..+16) * V[j*16..+16, :)
            #pragma unroll
            for (int ne = 0; ne < 8; ne++) {
                uint32_t bf[2];
                const uint32_t* vr = Vst + (ne * 8 + g) * VTS + j * 8 + t4;
                bf[0] = vr[0];
                bf[1] = vr[4];
                mma_bf16(oacc[ne], pa, bf);
            }
        }
        __syncthreads();
    }

    // row-sum reduction across the quad
    rs0 += __shfl_xor_sync(0xffffffffu, rs0, 1);
    rs0 += __shfl_xor_sync(0xffffffffu, rs0, 2);
    rs1 += __shfl_xor_sync(0xffffffffu, rs1, 1);
    rs1 += __shfl_xor_sync(0xffffffffu, rs1, 2);
    float inv0 = 1.0f / rs0, inv1 = 1.0f / rs1;

    #pragma unroll
    for (int nt = 0; nt < 8; nt++) {
        int cg = h * 64 + nt * 8 + t4 * 2;
        size_t o0 = (rowbase + qr0) * (size_t)DM + cg;
        size_t o1 = (rowbase + qr1) * (size_t)DM + cg;
        *(float2*)&g_o[o0] = make_float2(rna_tf32(oacc[nt][0] * inv0),
                                         rna_tf32(oacc[nt][1] * inv0));
        *(float2*)&g_o[o1] = make_float2(rna_tf32(oacc[nt][2] * inv1),
                                         rna_tf32(oacc[nt][3] * inv1));
    }
}

// ---------------- launch ----------------
extern "C" void kernel_launch(void* const* d_in, const int* in_sizes, int n_in,
                              void* d_out, int out_size) {
    const float* x     = (const float*)d_in[0];
    const float* Bb    = (const float*)d_in[1];
    const int*   Mm    = (const int*)  d_in[2];
    const float* gamma = (const float*)d_in[3];
    const float* beta  = (const float*)d_in[4];
    const float* wq    = (const float*)d_in[5];
    const float* wk    = (const float*)d_in[6];
    const float* wv    = (const float*)d_in[7];
    const float* wp    = (const float*)d_in[8];
    float* out = (float*)d_out;

    void *p_xn, *p_qkv, *p_o, *p_wb, *p_wpr;
    cudaGetSymbolAddress(&p_xn,  g_xn);
    cudaGetSymbolAddress(&p_qkv, g_qkv);
    cudaGetSymbolAddress(&p_o,   g_o);
    cudaGetSymbolAddress(&p_wb,  g_wb);
    cudaGetSymbolAddress(&p_wpr, g_wpr);

    const int gemm_smem  = GSTG * 2 * 4;    // 73728
    const int flash_smem = FSTG_B * 2;      // 53248
    cudaFuncSetAttribute(gemm_mma,     cudaFuncAttributeMaxDynamicSharedMemorySize, gemm_smem);
    cudaFuncSetAttribute(flash_kernel, cudaFuncAttributeMaxDynamicSharedMemorySize, flash_smem);

    ln_kernel<<<TR, 256>>>(x, gamma, beta);
    prep_w<<<4096, 256>>>(wq, wk, wv, wp);
    gemm_mma<<<dim3(TR / 128, 1536 / 128), 256, gemm_smem>>>(
        (const float*)p_xn, (const float*)p_wb, (float*)p_qkv, nullptr, 512, 1536, 1);
    vpack_kernel<<<dim3(16, 32), 256>>>();
    flash_kernel<<<dim3(THW / 64, 1, NH * BS), 128, flash_smem>>>(Bb, Mm);
    gemm_mma<<<dim3(TR / 128, DM / 128), 256, gemm_smem>>>(
        (const float*)p_o, (const float*)p_wpr, out, x, 512, DM, 0);
}

// round 6
// speedup vs baseline: 3.4863x; 1.1017x over previous
#include <cuda_runtime.h>
#include <cstdint>

#define THW 1024
#define DM  512
#define NH  8
#define DH  64
#define BS  4
#define TR  (BS*THW)       // 4096
#define LNEPS 1e-5f

// ---------------- scratch ----------------
__device__ float    g_xn [(size_t)TR * DM];
__device__ float    g_qkv[(size_t)TR * 1536];      // [row][ q(512) | k(512) | (v unused) ]
__device__ float    g_o  [(size_t)TR * DM];
__device__ float    g_wb [1536 * 512];             // QKV B operand [n][k], tf32
__device__ float    g_wpr[512 * 512];              // wp [n][k], tf32
__device__ uint32_t g_vt [(size_t)32 * 64 * 512];  // packed bf16 V^T: [z][e][cp], cp = c/2

// ---------------- helpers ----------------
__device__ __forceinline__ float rna_tf32(float v) {
    uint32_t u;
    asm("cvt.rna.tf32.f32 %0, %1;" : "=r"(u) : "f"(v));
    return __uint_as_float(u);
}
__device__ __forceinline__ uint32_t pack_bf16(float lo, float hi) {
    uint32_t r;
    asm("cvt.rn.bf16x2.f32 %0, %1, %2;" : "=r"(r) : "f"(hi), "f"(lo));
    return r;
}
__device__ __forceinline__ uint32_t smem_u32(const void* p) {
    uint32_t a;
    asm("{ .reg .u64 t; cvta.to.shared.u64 t, %1; cvt.u32.u64 %0, t; }" : "=r"(a) : "l"(p));
    return a;
}
__device__ __forceinline__ void cp16(uint32_t dst, const void* src) {
    asm volatile("cp.async.cg.shared.global [%0], [%1], 16;" :: "r"(dst), "l"(src));
}
__device__ __forceinline__ void cp_commit() { asm volatile("cp.async.commit_group;"); }

// D += A(16x8,row,tf32) * B(8x8,col,tf32)
__device__ __forceinline__ void mma_tf32(float d[4], const uint32_t a[4], const uint32_t b[2]) {
    asm volatile(
        "mma.sync.aligned.m16n8k8.row.col.f32.tf32.tf32.f32 "
        "{%0,%1,%2,%3}, {%4,%5,%6,%7}, {%8,%9}, {%0,%1,%2,%3};"
        : "+f"(d[0]), "+f"(d[1]), "+f"(d[2]), "+f"(d[3])
        : "r"(a[0]), "r"(a[1]), "r"(a[2]), "r"(a[3]), "r"(b[0]), "r"(b[1]));
}
// D += A(16x16,row,bf16) * B(16x8,col,bf16)
__device__ __forceinline__ void mma_bf16(float d[4], const uint32_t a[4], const uint32_t b[2]) {
    asm volatile(
        "mma.sync.aligned.m16n8k16.row.col.f32.bf16.bf16.f32 "
        "{%0,%1,%2,%3}, {%4,%5,%6,%7}, {%8,%9}, {%0,%1,%2,%3};"
        : "+f"(d[0]), "+f"(d[1]), "+f"(d[2]), "+f"(d[3])
        : "r"(a[0]), "r"(a[1]), "r"(a[2]), "r"(a[3]), "r"(b[0]), "r"(b[1]));
}

// ---------------- LayerNorm ----------------
__global__ void ln_kernel(const float* __restrict__ x,
                          const float* __restrict__ gamma,
                          const float* __restrict__ beta) {
    int row = blockIdx.x;
    const float* xr = x + (size_t)row * DM;
    int t = threadIdx.x;
    float v0 = xr[t], v1 = xr[t + 256];

    __shared__ float red[8];
    float s = v0 + v1;
    #pragma unroll
    for (int o = 16; o; o >>= 1) s += __shfl_xor_sync(0xffffffffu, s, o);
    if ((t & 31) == 0) red[t >> 5] = s;
    __syncthreads();
    if (t < 8) {
        float m = red[t];
        #pragma unroll
        for (int o = 4; o; o >>= 1) m += __shfl_xor_sync(0xffu, m, o);
        if (t == 0) red[0] = m;
    }
    __syncthreads();
    float mu = red[0] * (1.0f / DM);
    __syncthreads();

    float d0 = v0 - mu, d1 = v1 - mu;
    float s2 = d0 * d0 + d1 * d1;
    #pragma unroll
    for (int o = 16; o; o >>= 1) s2 += __shfl_xor_sync(0xffffffffu, s2, o);
    if ((t & 31) == 0) red[t >> 5] = s2;
    __syncthreads();
    if (t < 8) {
        float m = red[t];
        #pragma unroll
        for (int o = 4; o; o >>= 1) m += __shfl_xor_sync(0xffu, m, o);
        if (t == 0) red[0] = m;
    }
    __syncthreads();
    float rstd = rsqrtf(red[0] * (1.0f / DM) + LNEPS);

    float* xo = g_xn + (size_t)row * DM;
    xo[t]       = rna_tf32(d0 * rstd * gamma[t]       + beta[t]);
    xo[t + 256] = rna_tf32(d1 * rstd * gamma[t + 256] + beta[t + 256]);
}

// ---------------- prep: pack weights into tf32 B operands ----------------
__global__ void prep_w(const float* __restrict__ wq, const float* __restrict__ wk,
                       const float* __restrict__ wv, const float* __restrict__ wp) {
    size_t idx = (size_t)blockIdx.x * 256 + threadIdx.x;
    if (idx < (size_t)1536 * 512) {
        int n = (int)(idx >> 9), k = (int)(idx & 511);
        int sel = n >> 9;
        int he = n & 511;
        int h = he >> 6, e = he & 63;
        const float* w = sel == 0 ? wq : sel == 1 ? wk : wv;
        g_wb[idx] = rna_tf32(w[((size_t)h * 512 + k) * 64 + e]);
    } else {
        size_t i2 = idx - (size_t)1536 * 512;
        if (i2 < (size_t)512 * 512) g_wpr[i2] = rna_tf32(wp[i2]);
    }
}

// ---------------- tf32 MMA GEMM, 2-stage cp.async pipeline ----------------
// If vt != null and this n-block is in the V range (n0 >= 1024), the epilogue
// packs bf16 token-pairs transposed into g_vt instead of writing C.
#define PK 36
#define GSTG (128 * PK * 2)   // floats per stage (As + Bs)
__global__ __launch_bounds__(256) void gemm_mma(const float* __restrict__ A,
                                                const float* __restrict__ Bw,
                                                float* __restrict__ C,
                                                const float* __restrict__ res,
                                                uint32_t* __restrict__ vt,
                                                int K, int ldc, int round_out) {
    extern __shared__ float gsm[];
    int tid = threadIdx.x, lane = tid & 31, warp = tid >> 5;
    int wm = (warp >> 2) * 64;
    int wn = (warp & 3) * 32;
    int m0 = blockIdx.x * 128, n0 = blockIdx.y * 128;
    int g = lane >> 2, t4 = lane & 3;

    float acc[4][4][4] = {};
    int NK = K >> 5;

    auto fill = [&](int kt, int s) {
        const float* Ag = A  + (size_t)m0 * K + kt * 32;
        const float* Bg = Bw + (size_t)n0 * K + kt * 32;
        uint32_t ab = smem_u32(gsm + s * GSTG);
        uint32_t bb = ab + 128 * PK * 4;
        #pragma unroll
        for (int i = 0; i < 4; i++) {
            int c = tid + i * 256;
            int r = c >> 3, cc = c & 7;
            cp16(ab + (uint32_t)(r * PK + cc * 4) * 4, Ag + (size_t)r * K + cc * 4);
            cp16(bb + (uint32_t)(r * PK + cc * 4) * 4, Bg + (size_t)r * K + cc * 4);
        }
        cp_commit();
    };

    fill(0, 0);
    for (int kt = 0; kt < NK; kt++) {
        int st = kt & 1;
        if (kt + 1 < NK) {
            fill(kt + 1, st ^ 1);
            asm volatile("cp.async.wait_group 1;" ::: "memory");
        } else {
            asm volatile("cp.async.wait_group 0;" ::: "memory");
        }
        __syncthreads();
        const float* As = gsm + st * GSTG;
        const float* Bs = As + 128 * PK;
        #pragma unroll
        for (int ks = 0; ks < 4; ks++) {
            int k0 = ks * 8;
            uint32_t a[4][4], b[4][2];
            #pragma unroll
            for (int mt = 0; mt < 4; mt++) {
                int r = wm + mt * 16 + g;
                a[mt][0] = __float_as_uint(As[r * PK + k0 + t4]);
                a[mt][1] = __float_as_uint(As[(r + 8) * PK + k0 + t4]);
                a[mt][2] = __float_as_uint(As[r * PK + k0 + t4 + 4]);
                a[mt][3] = __float_as_uint(As[(r + 8) * PK + k0 + t4 + 4]);
            }
            #pragma unroll
            for (int nt = 0; nt < 4; nt++) {
                int n = wn + nt * 8 + g;
                b[nt][0] = __float_as_uint(Bs[n * PK + k0 + t4]);
                b[nt][1] = __float_as_uint(Bs[n * PK + k0 + t4 + 4]);
            }
            #pragma unroll
            for (int mt = 0; mt < 4; mt++)
                #pragma unroll
                for (int nt = 0; nt < 4; nt++)
                    mma_tf32(acc[mt][nt], a[mt], b[nt]);
        }
        __syncthreads();
    }

    if (vt && n0 >= 1024) {
        // ---- V epilogue: pack bf16 token-pairs transposed into g_vt ----
        bool geven = (g & 1) == 0;
        #pragma unroll
        for (int mt = 0; mt < 4; mt++) {
            int ra = m0 + wm + mt * 16 + g;      // global token row
            int b_ = ra >> 10, c_ = ra & 1023;
            #pragma unroll
            for (int nt = 0; nt < 4; nt++) {
                int np = n0 - 1024 + wn + nt * 8 + t4 * 2;
                int h_ = np >> 6, e0 = np & 63;
                int z_ = h_ * 4 + b_;
                float v0 = acc[mt][nt][0], v1 = acc[mt][nt][1];
                float v2 = acc[mt][nt][2], v3 = acc[mt][nt][3];
                float e0x = __shfl_xor_sync(0xffffffffu, v0, 4);
                float e1x = __shfl_xor_sync(0xffffffffu, v1, 4);
                float e2x = __shfl_xor_sync(0xffffffffu, v2, 4);
                float e3x = __shfl_xor_sync(0xffffffffu, v3, 4);
                size_t ebase = ((size_t)z_ * 64 + e0) * 512;
                if (geven) {
                    int cp = c_ >> 1;                       // pair (c, c+1)
                    vt[ebase + cp]        = pack_bf16(v0, e0x);
                    vt[ebase + 512 + cp]  = pack_bf16(v1, e1x);
                } else {
                    int cp = (c_ + 7) >> 1;                 // pair (c+7, c+8)
                    vt[ebase + cp]        = pack_bf16(e2x, v2);
                    vt[ebase + 512 + cp]  = pack_bf16(e3x, v3);
                }
            }
        }
        return;
    }

    #pragma unroll
    for (int mt = 0; mt < 4; mt++) {
        #pragma unroll
        for (int nt = 0; nt < 4; nt++) {
            int r = m0 + wm + mt * 16 + g;
            int c = n0 + wn + nt * 8 + t4 * 2;
            float v0 = acc[mt][nt][0], v1 = acc[mt][nt][1];
            float v2 = acc[mt][nt][2], v3 = acc[mt][nt][3];
            size_t o0 = (size_t)r * ldc + c;
            size_t o1 = (size_t)(r + 8) * ldc + c;
            if (res) {
                float2 r0 = *(const float2*)(res + o0);
                float2 r1 = *(const float2*)(res + o1);
                v0 += r0.x; v1 += r0.y; v2 += r1.x; v3 += r1.y;
            }
            if (round_out) {
                v0 = rna_tf32(v0); v1 = rna_tf32(v1);
                v2 = rna_tf32(v2); v3 = rna_tf32(v3);
            }
            *(float2*)(C + o0) = make_float2(v0, v1);
            *(float2*)(C + o1) = make_float2(v2, v3);
        }
    }
}

// ---------------- fused flash attention: tf32 QK^T, bf16 PV, 2-stage pipeline ----------------
// 256 threads, 128 q-rows per CTA (16 per warp), K/V tile streamed 64 cols at a time.
#define KPAD 68                 // Ks [c][e] float, banks 4g+t4 conflict-free
#define VTS  36                 // Vst [e][cp] uint32, banks 4g+t4 conflict-free
#define FSTG_B (64 * KPAD * 4 + 64 * VTS * 4)   // 26624 bytes per stage
__global__ __launch_bounds__(256, 2) void flash_kernel(const float* __restrict__ Bb,
                                                       const int* __restrict__ Mm) {
    extern __shared__ float smf[];
    int z = blockIdx.z;
    int h = z >> 2, b = z & 3;
    int q0 = blockIdx.x * 128;
    int tid = threadIdx.x, lane = tid & 31, warp = tid >> 5;
    int g = lane >> 2, t4 = lane & 3;

    size_t rowbase = (size_t)b * THW;
    int kcol = 512 + h * 64;
    uint32_t smbase = smem_u32(smf);

    // loop-invariant Q fragments (16 q-rows per warp)
    uint32_t qa[8][4];
    {
        const float* Q0 = g_qkv + (rowbase + q0 + warp * 16 + g) * 1536 + h * 64;
        const float* Q1 = Q0 + 8 * 1536;
        #pragma unroll
        for (int ks = 0; ks < 8; ks++) {
            int k = ks * 8 + t4;
            qa[ks][0] = __float_as_uint(Q0[k]);
            qa[ks][1] = __float_as_uint(Q1[k]);
            qa[ks][2] = __float_as_uint(Q0[k + 4]);
            qa[ks][3] = __float_as_uint(Q1[k + 4]);
        }
    }

    float oacc[8][4] = {};
    float rs0 = 0.f, rs1 = 0.f;
    const float* Bz = Bb + (size_t)z * THW * THW;
    int qr0 = q0 + warp * 16 + g;
    int qr1 = qr0 + 8;

    auto fill = [&](int it, int s) {
        int c0 = it * 64;
        uint32_t kb = smbase + s * FSTG_B;
        uint32_t vb = kb + 64 * KPAD * 4;
        #pragma unroll
        for (int i = 0; i < 4; i++) {
            int c = tid + i * 256;          // 0..1023 16B chunks of K tile
            int r = c >> 4, cc = c & 15;
            cp16(kb + (uint32_t)(r * KPAD + cc * 4) * 4,
                 g_qkv + (rowbase + c0 + r) * 1536 + kcol + cc * 4);
        }
        #pragma unroll
        for (int i = 0; i < 2; i++) {
            int c = tid + i * 256;          // 0..511 16B chunks of V tile
            int e = c >> 3, jj = c & 7;
            cp16(vb + (uint32_t)(e * VTS + jj * 4) * 4,
                 &g_vt[((size_t)(z * 64) + e) * 512 + (c0 >> 1) + jj * 4]);
        }
        cp_commit();
    };

    fill(0, 0);
    for (int it = 0; it < 16; it++) {
        int st = it & 1;
        int c0 = it * 64;
        if (it < 15) {
            fill(it + 1, st ^ 1);
            asm volatile("cp.async.wait_group 1;" ::: "memory");
        } else {
            asm volatile("cp.async.wait_group 0;" ::: "memory");
        }
        __syncthreads();
        const float* Ks = smf + st * (FSTG_B / 4);
        const uint32_t* Vst = (const uint32_t*)(Ks + 64 * KPAD);

        #pragma unroll
        for (int j = 0; j < 4; j++) {
            int ca = c0 + j * 16 + t4 * 2;
            size_t bo0 = (size_t)qr0 * THW + ca;
            size_t bo1 = (size_t)qr1 * THW + ca;
            float2 bA0 = *(const float2*)(Bz + bo0);
            float2 bA1 = *(const float2*)(Bz + bo1);
            float2 bB0 = *(const float2*)(Bz + bo0 + 8);
            float2 bB1 = *(const float2*)(Bz + bo1 + 8);
            int2 mA0 = *(const int2*)(Mm + bo0);
            int2 mA1 = *(const int2*)(Mm + bo1);
            int2 mB0 = *(const int2*)(Mm + bo0 + 8);
            int2 mB1 = *(const int2*)(Mm + bo1 + 8);

            float saccA[4] = {}, saccB[4] = {};
            const float* krA = Ks + (j * 16 + g) * KPAD;
            const float* krB = krA + 8 * KPAD;
            #pragma unroll
            for (int ks = 0; ks < 8; ks++) {
                uint32_t fA[2], fB[2];
                fA[0] = __float_as_uint(krA[ks * 8 + t4]);
                fA[1] = __float_as_uint(krA[ks * 8 + t4 + 4]);
                fB[0] = __float_as_uint(krB[ks * 8 + t4]);
                fB[1] = __float_as_uint(krB[ks * 8 + t4 + 4]);
                mma_tf32(saccA, qa[ks], fA);
                mma_tf32(saccB, qa[ks], fB);
            }

            float pA0 = mA0.x ? 0.f : __expf(fmaf(saccA[0], 0.125f, bA0.x));
            float pA1 = mA0.y ? 0.f : __expf(fmaf(saccA[1], 0.125f, bA0.y));
            float pA2 = mA1.x ? 0.f : __expf(fmaf(saccA[2], 0.125f, bA1.x));
            float pA3 = mA1.y ? 0.f : __expf(fmaf(saccA[3], 0.125f, bA1.y));
            float pB0 = mB0.x ? 0.f : __expf(fmaf(saccB[0], 0.125f, bB0.x));
            float pB1 = mB0.y ? 0.f : __expf(fmaf(saccB[1], 0.125f, bB0.y));
            float pB2 = mB1.x ? 0.f : __expf(fmaf(saccB[2], 0.125f, bB1.x));
            float pB3 = mB1.y ? 0.f : __expf(fmaf(saccB[3], 0.125f, bB1.y));
            rs0 += pA0 + pA1 + pB0 + pB1;
            rs1 += pA2 + pA3 + pB2 + pB3;

            uint32_t pa[4];
            pa[0] = pack_bf16(pA0, pA1);
            pa[1] = pack_bf16(pA2, pA3);
            pa[2] = pack_bf16(pB0, pB1);
            pa[3] = pack_bf16(pB2, pB3);

            #pragma unroll
            for (int ne = 0; ne < 8; ne++) {
                uint32_t bf[2];
                const uint32_t* vr = Vst + (ne * 8 + g) * VTS + j * 8 + t4;
                bf[0] = vr[0];
                bf[1] = vr[4];
                mma_bf16(oacc[ne], pa, bf);
            }
        }
        __syncthreads();
    }

    rs0 += __shfl_xor_sync(0xffffffffu, rs0, 1);
    rs0 += __shfl_xor_sync(0xffffffffu, rs0, 2);
    rs1 += __shfl_xor_sync(0xffffffffu, rs1, 1);
    rs1 += __shfl_xor_sync(0xffffffffu, rs1, 2);
    float inv0 = 1.0f / rs0, inv1 = 1.0f / rs1;

    #pragma unroll
    for (int nt = 0; nt < 8; nt++) {
        int cg = h * 64 + nt * 8 + t4 * 2;
        size_t o0 = (rowbase + qr0) * (size_t)DM + cg;
        size_t o1 = (rowbase + qr1) * (size_t)DM + cg;
        *(float2*)&g_o[o0] = make_float2(rna_tf32(oacc[nt][0] * inv0),
                                         rna_tf32(oacc[nt][1] * inv0));
        *(float2*)&g_o[o1] = make_float2(rna_tf32(oacc[nt][2] * inv1),
                                         rna_tf32(oacc[nt][3] * inv1));
    }
}

// ---------------- launch ----------------
extern "C" void kernel_launch(void* const* d_in, const int* in_sizes, int n_in,
                              void* d_out, int out_size) {
    const float* x     = (const float*)d_in[0];
    const float* Bb    = (const float*)d_in[1];
    const int*   Mm    = (const int*)  d_in[2];
    const float* gamma = (const float*)d_in[3];
    const float* beta  = (const float*)d_in[4];
    const float* wq    = (const float*)d_in[5];
    const float* wk    = (const float*)d_in[6];
    const float* wv    = (const float*)d_in[7];
    const float* wp    = (const float*)d_in[8];
    float* out = (float*)d_out;

    void *p_xn, *p_qkv, *p_o, *p_wb, *p_wpr, *p_vt;
    cudaGetSymbolAddress(&p_xn,  g_xn);
    cudaGetSymbolAddress(&p_qkv, g_qkv);
    cudaGetSymbolAddress(&p_o,   g_o);
    cudaGetSymbolAddress(&p_wb,  g_wb);
    cudaGetSymbolAddress(&p_wpr, g_wpr);
    cudaGetSymbolAddress(&p_vt,  g_vt);

    const int gemm_smem  = GSTG * 2 * 4;    // 73728
    const int flash_smem = FSTG_B * 2;      // 53248
    cudaFuncSetAttribute(gemm_mma,     cudaFuncAttributeMaxDynamicSharedMemorySize, gemm_smem);
    cudaFuncSetAttribute(flash_kernel, cudaFuncAttributeMaxDynamicSharedMemorySize, flash_smem);

    ln_kernel<<<TR, 256>>>(x, gamma, beta);
    prep_w<<<4096, 256>>>(wq, wk, wv, wp);
    gemm_mma<<<dim3(TR / 128, 1536 / 128), 256, gemm_smem>>>(
        (const float*)p_xn, (const float*)p_wb, (float*)p_qkv, nullptr,
        (uint32_t*)p_vt, 512, 1536, 1);
    flash_kernel<<<dim3(THW / 128, 1, NH * BS), 256, flash_smem>>>(Bb, Mm);
    gemm_mma<<<dim3(TR / 128, DM / 128), 256, gemm_smem>>>(
        (const float*)p_o, (const float*)p_wpr, out, x, nullptr, 512, DM, 0);
}

// round 7
// speedup vs baseline: 3.7342x; 1.0711x over previous
#include <cuda_runtime.h>
#include <cstdint>

#define THW 1024
#define DM  512
#define NH  8
#define DH  64
#define BS  4
#define TR  (BS*THW)       // 4096
#define LNEPS 1e-5f

// within-8-group permutation that makes MMA k-pairs (r, r+4) adjacent: p=2r / 2r-7
__host__ __device__ __forceinline__ int perm3(int r) { return (r < 4) ? 2 * r : 2 * r - 7; }

// ---------------- scratch ----------------
__device__ float    g_xn [(size_t)TR * DM];        // LN out, k-permuted
__device__ float    g_qkv[(size_t)TR * 1536];      // [row][ q|k|(v unused) ], q/k e-permuted
__device__ float    g_o  [(size_t)TR * DM];        // concat attn out, feature-permuted
__device__ float    g_wb [1536 * 512];             // QKV B [n][k]: k-perm all, n-perm for q/k
__device__ float    g_wpr[512 * 512];              // wp [n][k], k-permuted
__device__ uint32_t g_vt [(size_t)32 * 64 * 512];  // bf16x2 V^T [z][e][cp], cp-pair-permuted

// ---------------- helpers ----------------
__device__ __forceinline__ float rna_tf32(float v) {
    uint32_t u;
    asm("cvt.rna.tf32.f32 %0, %1;" : "=r"(u) : "f"(v));
    return __uint_as_float(u);
}
__device__ __forceinline__ uint32_t pack_bf16(float lo, float hi) {
    uint32_t r;
    asm("cvt.rn.bf16x2.f32 %0, %1, %2;" : "=r"(r) : "f"(hi), "f"(lo));
    return r;
}
__device__ __forceinline__ uint32_t smem_u32(const void* p) {
    uint32_t a;
    asm("{ .reg .u64 t; cvta.to.shared.u64 t, %1; cvt.u32.u64 %0, t; }" : "=r"(a) : "l"(p));
    return a;
}
__device__ __forceinline__ void cp16(uint32_t dst, const void* src) {
    asm volatile("cp.async.cg.shared.global [%0], [%1], 16;" :: "r"(dst), "l"(src));
}
__device__ __forceinline__ void cp_commit() { asm volatile("cp.async.commit_group;"); }

__device__ __forceinline__ void mma_tf32(float d[4], const uint32_t a[4], const uint32_t b[2]) {
    asm volatile(
        "mma.sync.aligned.m16n8k8.row.col.f32.tf32.tf32.f32 "
        "{%0,%1,%2,%3}, {%4,%5,%6,%7}, {%8,%9}, {%0,%1,%2,%3};"
        : "+f"(d[0]), "+f"(d[1]), "+f"(d[2]), "+f"(d[3])
        : "r"(a[0]), "r"(a[1]), "r"(a[2]), "r"(a[3]), "r"(b[0]), "r"(b[1]));
}
__device__ __forceinline__ void mma_bf16(float d[4], const uint32_t a[4], const uint32_t b[2]) {
    asm volatile(
        "mma.sync.aligned.m16n8k16.row.col.f32.bf16.bf16.f32 "
        "{%0,%1,%2,%3}, {%4,%5,%6,%7}, {%8,%9}, {%0,%1,%2,%3};"
        : "+f"(d[0]), "+f"(d[1]), "+f"(d[2]), "+f"(d[3])
        : "r"(a[0]), "r"(a[1]), "r"(a[2]), "r"(a[3]), "r"(b[0]), "r"(b[1]));
}

// ---------------- LayerNorm (k-permuted output) ----------------
__global__ void ln_kernel(const float* __restrict__ x,
                          const float* __restrict__ gamma,
                          const float* __restrict__ beta) {
    int row = blockIdx.x;
    const float* xr = x + (size_t)row * DM;
    int t = threadIdx.x;
    float v0 = xr[t], v1 = xr[t + 256];

    __shared__ float red[8];
    float s = v0 + v1;
    #pragma unroll
    for (int o = 16; o; o >>= 1) s += __shfl_xor_sync(0xffffffffu, s, o);
    if ((t & 31) == 0) red[t >> 5] = s;
    __syncthreads();
    if (t < 8) {
        float m = red[t];
        #pragma unroll
        for (int o = 4; o; o >>= 1) m += __shfl_xor_sync(0xffu, m, o);
        if (t == 0) red[0] = m;
    }
    __syncthreads();
    float mu = red[0] * (1.0f / DM);
    __syncthreads();

    float d0 = v0 - mu, d1 = v1 - mu;
    float s2 = d0 * d0 + d1 * d1;
    #pragma unroll
    for (int o = 16; o; o >>= 1) s2 += __shfl_xor_sync(0xffffffffu, s2, o);
    if ((t & 31) == 0) red[t >> 5] = s2;
    __syncthreads();
    if (t < 8) {
        float m = red[t];
        #pragma unroll
        for (int o = 4; o; o >>= 1) m += __shfl_xor_sync(0xffu, m, o);
        if (t == 0) red[0] = m;
    }
    __syncthreads();
    float rstd = rsqrtf(red[0] * (1.0f / DM) + LNEPS);

    float* xo = g_xn + (size_t)row * DM;
    int tp = (t & ~7) | perm3(t & 7);
    xo[tp]       = rna_tf32(d0 * rstd * gamma[t]       + beta[t]);
    xo[tp + 256] = rna_tf32(d1 * rstd * gamma[t + 256] + beta[t + 256]);
}

// ---------------- prep: pack weights (k-perm; n-perm for q/k sections) ----------------
__global__ void prep_w(const float* __restrict__ wq, const float* __restrict__ wk,
                       const float* __restrict__ wv, const float* __restrict__ wp) {
    size_t idx = (size_t)blockIdx.x * 256 + threadIdx.x;
    if (idx < (size_t)1536 * 512) {
        int n = (int)(idx >> 9), k = (int)(idx & 511);
        int sel = n >> 9;
        int he = n & 511;
        int h = he >> 6, e = he & 63;
        const float* w = sel == 0 ? wq : sel == 1 ? wk : wv;
        float v = rna_tf32(w[((size_t)h * 512 + k) * 64 + e]);
        int kp = (k & ~7) | perm3(k & 7);
        int np = (sel < 2) ? ((n & ~7) | perm3(n & 7)) : n;
        g_wb[(size_t)np * 512 + kp] = v;
    } else {
        size_t i2 = idx - (size_t)1536 * 512;
        if (i2 < (size_t)512 * 512) {
            int n = (int)(i2 >> 9), k = (int)(i2 & 511);
            int kp = (k & ~7) | perm3(k & 7);
            g_wpr[(size_t)n * 512 + kp] = rna_tf32(wp[i2]);
        }
    }
}

// ---------------- tf32 MMA GEMM, 2-stage cp.async, LDS.64 fragments ----------------
// NSUB = 8-col n-subtiles per warp; block tile = 128 x (NSUB*32).
#define PK 40
template <int NSUB>
__global__ __launch_bounds__(256) void gemm_mma(const float* __restrict__ A,
                                                const float* __restrict__ Bw,
                                                float* __restrict__ C,
                                                const float* __restrict__ res,
                                                uint32_t* __restrict__ vt,
                                                int K, int ldc, int round_out) {
    constexpr int NBLK = NSUB * 32;
    constexpr int GSTG = (128 + NBLK) * PK;   // floats per stage
    extern __shared__ float gsm[];
    int tid = threadIdx.x, lane = tid & 31, warp = tid >> 5;
    int wm = (warp >> 2) * 64;
    int wn = (warp & 3) * NSUB * 8;
    int m0 = blockIdx.x * 128, n0 = blockIdx.y * NBLK;
    int g = lane >> 2, t4 = lane & 3;

    float acc[4][NSUB][4] = {};
    int NK = K >> 5;

    auto fill = [&](int kt, int s) {
        const float* Ag = A  + (size_t)m0 * K + kt * 32;
        const float* Bg = Bw + (size_t)n0 * K + kt * 32;
        uint32_t ab = smem_u32(gsm + s * GSTG);
        uint32_t bb = ab + 128 * PK * 4;
        #pragma unroll
        for (int i = 0; i < 4; i++) {
            int c = tid + i * 256;
            int r = c >> 3, cc = c & 7;
            cp16(ab + (uint32_t)(r * PK + cc * 4) * 4, Ag + (size_t)r * K + cc * 4);
        }
        #pragma unroll
        for (int i = 0; i < NSUB; i++) {
            int c = tid + i * 256;
            int r = c >> 3, cc = c & 7;
            cp16(bb + (uint32_t)(r * PK + cc * 4) * 4, Bg + (size_t)r * K + cc * 4);
        }
        cp_commit();
    };

    fill(0, 0);
    for (int kt = 0; kt < NK; kt++) {
        int st = kt & 1;
        if (kt + 1 < NK) {
            fill(kt + 1, st ^ 1);
            asm volatile("cp.async.wait_group 1;" ::: "memory");
        } else {
            asm volatile("cp.async.wait_group 0;" ::: "memory");
        }
        __syncthreads();
        const float* As = gsm + st * GSTG;
        const float* Bs = As + 128 * PK;
        #pragma unroll
        for (int ks = 0; ks < 4; ks++) {
            int k0 = ks * 8;
            uint32_t a[4][4], b[NSUB][2];
            #pragma unroll
            for (int mt = 0; mt < 4; mt++) {
                int r = wm + mt * 16 + g;
                float2 a0 = *(const float2*)(As + r * PK + k0 + 2 * t4);
                float2 a1 = *(const float2*)(As + (r + 8) * PK + k0 + 2 * t4);
                a[mt][0] = __float_as_uint(a0.x);
                a[mt][1] = __float_as_uint(a1.x);
                a[mt][2] = __float_as_uint(a0.y);
                a[mt][3] = __float_as_uint(a1.y);
            }
            #pragma unroll
            for (int nt = 0; nt < NSUB; nt++) {
                int n = wn + nt * 8 + g;
                float2 bv = *(const float2*)(Bs + n * PK + k0 + 2 * t4);
                b[nt][0] = __float_as_uint(bv.x);
                b[nt][1] = __float_as_uint(bv.y);
            }
            #pragma unroll
            for (int mt = 0; mt < 4; mt++)
                #pragma unroll
                for (int nt = 0; nt < NSUB; nt++)
                    mma_tf32(acc[mt][nt], a[mt], b[nt]);
        }
        __syncthreads();
    }

    if (vt && n0 >= 1024) {
        // ---- V epilogue: pack bf16 token-pairs transposed into g_vt (cp-pair perm) ----
        bool geven = (g & 1) == 0;
        #pragma unroll
        for (int mt = 0; mt < 4; mt++) {
            int ra = m0 + wm + mt * 16 + g;
            int b_ = ra >> 10, c_ = ra & 1023;
            #pragma unroll
            for (int nt = 0; nt < NSUB; nt++) {
                int np = n0 - 1024 + wn + nt * 8 + t4 * 2;
                int h_ = np >> 6, e0 = np & 63;
                int z_ = h_ * 4 + b_;
                float v0 = acc[mt][nt][0], v1 = acc[mt][nt][1];
                float v2 = acc[mt][nt][2], v3 = acc[mt][nt][3];
                float e0x = __shfl_xor_sync(0xffffffffu, v0, 4);
                float e1x = __shfl_xor_sync(0xffffffffu, v1, 4);
                float e2x = __shfl_xor_sync(0xffffffffu, v2, 4);
                float e3x = __shfl_xor_sync(0xffffffffu, v3, 4);
                size_t ebase = ((size_t)z_ * 64 + e0) * 512;
                if (geven) {
                    int cp = c_ >> 1;
                    int cps = (cp & ~7) | perm3(cp & 7);
                    vt[ebase + cps]       = pack_bf16(v0, e0x);
                    vt[ebase + 512 + cps] = pack_bf16(v1, e1x);
                } else {
                    int cp = (c_ + 7) >> 1;
                    int cps = (cp & ~7) | perm3(cp & 7);
                    vt[ebase + cps]       = pack_bf16(e2x, v2);
                    vt[ebase + 512 + cps] = pack_bf16(e3x, v3);
                }
            }
        }
        return;
    }

    #pragma unroll
    for (int mt = 0; mt < 4; mt++) {
        #pragma unroll
        for (int nt = 0; nt < NSUB; nt++) {
            int r = m0 + wm + mt * 16 + g;
            int c = n0 + wn + nt * 8 + t4 * 2;
            float v0 = acc[mt][nt][0], v1 = acc[mt][nt][1];
            float v2 = acc[mt][nt][2], v3 = acc[mt][nt][3];
            size_t o0 = (size_t)r * ldc + c;
            size_t o1 = (size_t)(r + 8) * ldc + c;
            if (res) {
                float2 r0 = *(const float2*)(res + o0);
                float2 r1 = *(const float2*)(res + o1);
                v0 += r0.x; v1 += r0.y; v2 += r1.x; v3 += r1.y;
            }
            if (round_out) {
                v0 = rna_tf32(v0); v1 = rna_tf32(v1);
                v2 = rna_tf32(v2); v3 = rna_tf32(v3);
            }
            *(float2*)(C + o0) = make_float2(v0, v1);
            *(float2*)(C + o1) = make_float2(v2, v3);
        }
    }
}

// ---------------- fused flash attention: tf32 QK^T, bf16 PV, LDS.64 frags ----------------
#define KPAD 72                 // stride ≡ 8 (mod 32): LDS.64 conflict-free
#define VTS  40                 // same
#define FSTG_B (64 * KPAD * 4 + 64 * VTS * 4)   // 28672 bytes per stage
__global__ __launch_bounds__(256, 2) void flash_kernel(const float* __restrict__ Bb,
                                                       const int* __restrict__ Mm) {
    extern __shared__ float smf[];
    int z = blockIdx.z;
    int h = z >> 2, b = z & 3;
    int q0 = blockIdx.x * 128;
    int tid = threadIdx.x, lane = tid & 31, warp = tid >> 5;
    int g = lane >> 2, t4 = lane & 3;

    size_t rowbase = (size_t)b * THW;
    int kcol = 512 + h * 64;
    uint32_t smbase = smem_u32(smf);

    // loop-invariant Q fragments (e-permuted storage -> vector pair loads)
    uint32_t qa[8][4];
    {
        const float* Q0 = g_qkv + (rowbase + q0 + warp * 16 + g) * 1536 + h * 64;
        const float* Q1 = Q0 + 8 * 1536;
        #pragma unroll
        for (int ks = 0; ks < 8; ks++) {
            float2 f0 = *(const float2*)(Q0 + ks * 8 + 2 * t4);
            float2 f1 = *(const float2*)(Q1 + ks * 8 + 2 * t4);
            qa[ks][0] = __float_as_uint(f0.x);
            qa[ks][1] = __float_as_uint(f1.x);
            qa[ks][2] = __float_as_uint(f0.y);
            qa[ks][3] = __float_as_uint(f1.y);
        }
    }

    float oacc[8][4] = {};
    float rs0 = 0.f, rs1 = 0.f;
    const float* Bz = Bb + (size_t)z * THW * THW;
    int qr0 = q0 + warp * 16 + g;
    int qr1 = qr0 + 8;

    auto fill = [&](int it, int s) {
        int c0 = it * 64;
        uint32_t kb = smbase + s * FSTG_B;
        uint32_t vb = kb + 64 * KPAD * 4;
        #pragma unroll
        for (int i = 0; i < 4; i++) {
            int c = tid + i * 256;
            int r = c >> 4, cc = c & 15;
            cp16(kb + (uint32_t)(r * KPAD + cc * 4) * 4,
                 g_qkv + (rowbase + c0 + r) * 1536 + kcol + cc * 4);
        }
        #pragma unroll
        for (int i = 0; i < 2; i++) {
            int c = tid + i * 256;
            int e = c >> 3, jj = c & 7;
            cp16(vb + (uint32_t)(e * VTS + jj * 4) * 4,
                 &g_vt[((size_t)(z * 64) + e) * 512 + (c0 >> 1) + jj * 4]);
        }
        cp_commit();
    };

    fill(0, 0);
    for (int it = 0; it < 16; it++) {
        int st = it & 1;
        int c0 = it * 64;
        if (it < 15) {
            fill(it + 1, st ^ 1);
            asm volatile("cp.async.wait_group 1;" ::: "memory");
        } else {
            asm volatile("cp.async.wait_group 0;" ::: "memory");
        }
        __syncthreads();
        const float* Ks = smf + st * (FSTG_B / 4);
        const uint32_t* Vst = (const uint32_t*)(Ks + 64 * KPAD);

        #pragma unroll
        for (int j = 0; j < 4; j++) {
            int ca = c0 + j * 16 + t4 * 2;
            size_t bo0 = (size_t)qr0 * THW + ca;
            size_t bo1 = (size_t)qr1 * THW + ca;
            float2 bA0 = *(const float2*)(Bz + bo0);
            float2 bA1 = *(const float2*)(Bz + bo1);
            float2 bB0 = *(const float2*)(Bz + bo0 + 8);
            float2 bB1 = *(const float2*)(Bz + bo1 + 8);
            int2 mA0 = *(const int2*)(Mm + bo0);
            int2 mA1 = *(const int2*)(Mm + bo1);
            int2 mB0 = *(const int2*)(Mm + bo0 + 8);
            int2 mB1 = *(const int2*)(Mm + bo1 + 8);

            float saccA[4] = {}, saccB[4] = {};
            const float* krA = Ks + (j * 16 + g) * KPAD;
            const float* krB = krA + 8 * KPAD;
            #pragma unroll
            for (int ks = 0; ks < 8; ks++) {
                float2 fa = *(const float2*)(krA + ks * 8 + 2 * t4);
                float2 fb = *(const float2*)(krB + ks * 8 + 2 * t4);
                uint32_t fA[2] = { __float_as_uint(fa.x), __float_as_uint(fa.y) };
                uint32_t fB[2] = { __float_as_uint(fb.x), __float_as_uint(fb.y) };
                mma_tf32(saccA, qa[ks], fA);
                mma_tf32(saccB, qa[ks], fB);
            }

            float pA0 = mA0.x ? 0.f : __expf(fmaf(saccA[0], 0.125f, bA0.x));
            float pA1 = mA0.y ? 0.f : __expf(fmaf(saccA[1], 0.125f, bA0.y));
            float pA2 = mA1.x ? 0.f : __expf(fmaf(saccA[2], 0.125f, bA1.x));
            float pA3 = mA1.y ? 0.f : __expf(fmaf(saccA[3], 0.125f, bA1.y));
            float pB0 = mB0.x ? 0.f : __expf(fmaf(saccB[0], 0.125f, bB0.x));
            float pB1 = mB0.y ? 0.f : __expf(fmaf(saccB[1], 0.125f, bB0.y));
            float pB2 = mB1.x ? 0.f : __expf(fmaf(saccB[2], 0.125f, bB1.x));
            float pB3 = mB1.y ? 0.f : __expf(fmaf(saccB[3], 0.125f, bB1.y));
            rs0 += pA0 + pA1 + pB0 + pB1;
            rs1 += pA2 + pA3 + pB2 + pB3;

            uint32_t pa[4];
            pa[0] = pack_bf16(pA0, pA1);
            pa[1] = pack_bf16(pA2, pA3);
            pa[2] = pack_bf16(pB0, pB1);
            pa[3] = pack_bf16(pB2, pB3);

            #pragma unroll
            for (int ne = 0; ne < 8; ne++) {
                uint2 bv = *(const uint2*)(Vst + (ne * 8 + g) * VTS + j * 8 + 2 * t4);
                uint32_t bf[2] = { bv.x, bv.y };
                mma_bf16(oacc[ne], pa, bf);
            }
        }
        __syncthreads();
    }

    rs0 += __shfl_xor_sync(0xffffffffu, rs0, 1);
    rs0 += __shfl_xor_sync(0xffffffffu, rs0, 2);
    rs1 += __shfl_xor_sync(0xffffffffu, rs1, 1);
    rs1 += __shfl_xor_sync(0xffffffffu, rs1, 2);
    float inv0 = 1.0f / rs0, inv1 = 1.0f / rs1;

    // store O feature-permuted (k-dim of proj GEMM); scalar stores (perm breaks pairs)
    size_t orow0 = (rowbase + qr0) * (size_t)DM;
    size_t orow1 = (rowbase + qr1) * (size_t)DM;
    #pragma unroll
    for (int nt = 0; nt < 8; nt++) {
        int base8 = h * 64 + nt * 8;
        int p0 = base8 + perm3(2 * t4);
        int p1 = base8 + perm3(2 * t4 + 1);
        g_o[orow0 + p0] = rna_tf32(oacc[nt][0] * inv0);
        g_o[orow0 + p1] = rna_tf32(oacc[nt][1] * inv0);
        g_o[orow1 + p0] = rna_tf32(oacc[nt][2] * inv1);
        g_o[orow1 + p1] = rna_tf32(oacc[nt][3] * inv1);
    }
}

// ---------------- launch ----------------
extern "C" void kernel_launch(void* const* d_in, const int* in_sizes, int n_in,
                              void* d_out, int out_size) {
    const float* x     = (const float*)d_in[0];
    const float* Bb    = (const float*)d_in[1];
    const int*   Mm    = (const int*)  d_in[2];
    const float* gamma = (const float*)d_in[3];
    const float* beta  = (const float*)d_in[4];
    const float* wq    = (const float*)d_in[5];
    const float* wk    = (const float*)d_in[6];
    const float* wv    = (const float*)d_in[7];
    const float* wp    = (const float*)d_in[8];
    float* out = (float*)d_out;

    void *p_xn, *p_qkv, *p_o, *p_wb, *p_wpr, *p_vt;
    cudaGetSymbolAddress(&p_xn,  g_xn);
    cudaGetSymbolAddress(&p_qkv, g_qkv);
    cudaGetSymbolAddress(&p_o,   g_o);
    cudaGetSymbolAddress(&p_wb,  g_wb);
    cudaGetSymbolAddress(&p_wpr, g_wpr);
    cudaGetSymbolAddress(&p_vt,  g_vt);

    const int gemm4_smem = (128 + 128) * PK * 2 * 4;   // 81920
    const int gemm2_smem = (128 + 64)  * PK * 2 * 4;   // 61440
    const int flash_smem = FSTG_B * 2;                 // 57344
    cudaFuncSetAttribute(gemm_mma<4>,  cudaFuncAttributeMaxDynamicSharedMemorySize, gemm4_smem);
    cudaFuncSetAttribute(gemm_mma<2>,  cudaFuncAttributeMaxDynamicSharedMemorySize, gemm2_smem);
    cudaFuncSetAttribute(flash_kernel, cudaFuncAttributeMaxDynamicSharedMemorySize, flash_smem);

    ln_kernel<<<TR, 256>>>(x, gamma, beta);
    prep_w<<<4096, 256>>>(wq, wk, wv, wp);
    gemm_mma<4><<<dim3(TR / 128, 1536 / 128), 256, gemm4_smem>>>(
        (const float*)p_xn, (const float*)p_wb, (float*)p_qkv, nullptr,
        (uint32_t*)p_vt, 512, 1536, 1);
    flash_kernel<<<dim3(THW / 128, 1, NH * BS), 256, flash_smem>>>(Bb, Mm);
    gemm_mma<2><<<dim3(TR / 128, DM / 64), 256, gemm2_smem>>>(
        (const float*)p_o, (const float*)p_wpr, out, x, nullptr, 512, DM, 0);
}

// round 8
// speedup vs baseline: 4.4029x; 1.1791x over previous
#include <cuda_runtime.h>
#include <cstdint>

#define THW 1024
#define DM  512
#define NH  8
#define DH  64
#define BS  4
#define TR  (BS*THW)       // 4096
#define LNEPS 1e-5f

// within-8-group permutation making MMA frag pairs (t4, t4+4) adjacent
__host__ __device__ __forceinline__ int perm3(int r) { return (r < 4) ? 2 * r : 2 * r - 7; }

// ---------------- scratch ----------------
__device__ float    g_xn [(size_t)TR * DM];        // LN out, k-permuted, tf32
__device__ uint32_t g_qk [(size_t)TR * 512];       // fp16x2 Q|K: [row][h*64 + (k?32:0) + word]
__device__ float    g_o  [(size_t)TR * DM];        // concat attn out, feature-permuted
__device__ float    g_wb [1536 * 512];             // QKV B [n][k], k-permuted, tf32
__device__ float    g_wpr[512 * 512];              // wp [n][k], k-permuted, tf32
__device__ uint32_t g_vt [(size_t)32 * 64 * 512];  // bf16x2 V^T [z][e][cp], cp-pair-permuted
__device__ uint32_t g_mb [1024 * 32];              // M bit-packed: bit c of word [q][c/32]

// ---------------- helpers ----------------
__device__ __forceinline__ float rna_tf32(float v) {
    uint32_t u;
    asm("cvt.rna.tf32.f32 %0, %1;" : "=r"(u) : "f"(v));
    return __uint_as_float(u);
}
__device__ __forceinline__ uint32_t pack_bf16(float lo, float hi) {
    uint32_t r;
    asm("cvt.rn.bf16x2.f32 %0, %1, %2;" : "=r"(r) : "f"(hi), "f"(lo));
    return r;
}
__device__ __forceinline__ uint32_t pack_f16(float lo, float hi) {
    uint32_t r;
    asm("cvt.rn.f16x2.f32 %0, %1, %2;" : "=r"(r) : "f"(hi), "f"(lo));
    return r;
}
__device__ __forceinline__ uint32_t smem_u32(const void* p) {
    uint32_t a;
    asm("{ .reg .u64 t; cvta.to.shared.u64 t, %1; cvt.u32.u64 %0, t; }" : "=r"(a) : "l"(p));
    return a;
}
__device__ __forceinline__ void cp16(uint32_t dst, const void* src) {
    asm volatile("cp.async.cg.shared.global [%0], [%1], 16;" :: "r"(dst), "l"(src));
}
__device__ __forceinline__ void cp_commit() { asm volatile("cp.async.commit_group;"); }

__device__ __forceinline__ void mma_tf32(float d[4], const uint32_t a[4], const uint32_t b[2]) {
    asm volatile(
        "mma.sync.aligned.m16n8k8.row.col.f32.tf32.tf32.f32 "
        "{%0,%1,%2,%3}, {%4,%5,%6,%7}, {%8,%9}, {%0,%1,%2,%3};"
        : "+f"(d[0]), "+f"(d[1]), "+f"(d[2]), "+f"(d[3])
        : "r"(a[0]), "r"(a[1]), "r"(a[2]), "r"(a[3]), "r"(b[0]), "r"(b[1]));
}
__device__ __forceinline__ void mma_f16(float d[4], const uint32_t a[4], uint32_t b0, uint32_t b1) {
    asm volatile(
        "mma.sync.aligned.m16n8k16.row.col.f32.f16.f16.f32 "
        "{%0,%1,%2,%3}, {%4,%5,%6,%7}, {%8,%9}, {%0,%1,%2,%3};"
        : "+f"(d[0]), "+f"(d[1]), "+f"(d[2]), "+f"(d[3])
        : "r"(a[0]), "r"(a[1]), "r"(a[2]), "r"(a[3]), "r"(b0), "r"(b1));
}
__device__ __forceinline__ void mma_bf16(float d[4], const uint32_t a[4], uint32_t b0, uint32_t b1) {
    asm volatile(
        "mma.sync.aligned.m16n8k16.row.col.f32.bf16.bf16.f32 "
        "{%0,%1,%2,%3}, {%4,%5,%6,%7}, {%8,%9}, {%0,%1,%2,%3};"
        : "+f"(d[0]), "+f"(d[1]), "+f"(d[2]), "+f"(d[3])
        : "r"(a[0]), "r"(a[1]), "r"(a[2]), "r"(a[3]), "r"(b0), "r"(b1));
}

// ---------------- LayerNorm (k-permuted tf32 output) ----------------
__global__ void ln_kernel(const float* __restrict__ x,
                          const float* __restrict__ gamma,
                          const float* __restrict__ beta) {
    int row = blockIdx.x;
    const float* xr = x + (size_t)row * DM;
    int t = threadIdx.x;
    float v0 = xr[t], v1 = xr[t + 256];

    __shared__ float red[8];
    float s = v0 + v1;
    #pragma unroll
    for (int o = 16; o; o >>= 1) s += __shfl_xor_sync(0xffffffffu, s, o);
    if ((t & 31) == 0) red[t >> 5] = s;
    __syncthreads();
    if (t < 8) {
        float m = red[t];
        #pragma unroll
        for (int o = 4; o; o >>= 1) m += __shfl_xor_sync(0xffu, m, o);
        if (t == 0) red[0] = m;
    }
    __syncthreads();
    float mu = red[0] * (1.0f / DM);
    __syncthreads();

    float d0 = v0 - mu, d1 = v1 - mu;
    float s2 = d0 * d0 + d1 * d1;
    #pragma unroll
    for (int o = 16; o; o >>= 1) s2 += __shfl_xor_sync(0xffffffffu, s2, o);
    if ((t & 31) == 0) red[t >> 5] = s2;
    __syncthreads();
    if (t < 8) {
        float m = red[t];
        #pragma unroll
        for (int o = 4; o; o >>= 1) m += __shfl_xor_sync(0xffu, m, o);
        if (t == 0) red[0] = m;
    }
    __syncthreads();
    float rstd = rsqrtf(red[0] * (1.0f / DM) + LNEPS);

    float* xo = g_xn + (size_t)row * DM;
    int tp = (t & ~7) | perm3(t & 7);
    xo[tp]       = rna_tf32(d0 * rstd * gamma[t]       + beta[t]);
    xo[tp + 256] = rna_tf32(d1 * rstd * gamma[t + 256] + beta[t + 256]);
}

// ---------------- prep: weights (k-perm only) + mask bitpack ----------------
__global__ void prep_w(const float* __restrict__ wq, const float* __restrict__ wk,
                       const float* __restrict__ wv, const float* __restrict__ wp) {
    size_t idx = (size_t)blockIdx.x * 256 + threadIdx.x;
    if (idx < (size_t)1536 * 512) {
        int n = (int)(idx >> 9), k = (int)(idx & 511);
        int sel = n >> 9;
        int he = n & 511;
        int h = he >> 6, e = he & 63;
        const float* w = sel == 0 ? wq : sel == 1 ? wk : wv;
        int kp = (k & ~7) | perm3(k & 7);
        g_wb[(size_t)n * 512 + kp] = rna_tf32(w[((size_t)h * 512 + k) * 64 + e]);
    } else {
        size_t i2 = idx - (size_t)1536 * 512;
        if (i2 < (size_t)512 * 512) {
            int n = (int)(i2 >> 9), k = (int)(i2 & 511);
            int kp = (k & ~7) | perm3(k & 7);
            g_wpr[(size_t)n * 512 + kp] = rna_tf32(wp[i2]);
        }
    }
}

__global__ void prep_mask(const int* __restrict__ M) {
    int idx = blockIdx.x * 256 + threadIdx.x;   // 0 .. 1024*1024-1
    bool m = M[idx] != 0;
    uint32_t w = __ballot_sync(0xffffffffu, m);
    if ((idx & 31) == 0) g_mb[idx >> 5] = w;
}

// ---------------- tf32 MMA GEMM, 2-stage cp.async, LDS.64 fragments ----------------
// qk/vt non-null => QKV mode: epilogue packs Q/K to fp16x2 in g_qk, V to bf16x2 in g_vt.
#define PK 40
template <int NSUB>
__global__ __launch_bounds__(256) void gemm_mma(const float* __restrict__ A,
                                                const float* __restrict__ Bw,
                                                float* __restrict__ C,
                                                const float* __restrict__ res,
                                                uint32_t* __restrict__ qk,
                                                uint32_t* __restrict__ vt,
                                                int K, int ldc, int round_out) {
    constexpr int NBLK = NSUB * 32;
    constexpr int GSTG = (128 + NBLK) * PK;
    extern __shared__ float gsm[];
    int tid = threadIdx.x, lane = tid & 31, warp = tid >> 5;
    int wm = (warp >> 2) * 64;
    int wn = (warp & 3) * NSUB * 8;
    int m0 = blockIdx.x * 128, n0 = blockIdx.y * NBLK;
    int g = lane >> 2, t4 = lane & 3;

    float acc[4][NSUB][4] = {};
    int NK = K >> 5;

    auto fill = [&](int kt, int s) {
        const float* Ag = A  + (size_t)m0 * K + kt * 32;
        const float* Bg = Bw + (size_t)n0 * K + kt * 32;
        uint32_t ab = smem_u32(gsm + s * GSTG);
        uint32_t bb = ab + 128 * PK * 4;
        #pragma unroll
        for (int i = 0; i < 4; i++) {
            int c = tid + i * 256;
            int r = c >> 3, cc = c & 7;
            cp16(ab + (uint32_t)(r * PK + cc * 4) * 4, Ag + (size_t)r * K + cc * 4);
        }
        #pragma unroll
        for (int i = 0; i < NSUB; i++) {
            int c = tid + i * 256;
            int r = c >> 3, cc = c & 7;
            cp16(bb + (uint32_t)(r * PK + cc * 4) * 4, Bg + (size_t)r * K + cc * 4);
        }
        cp_commit();
    };

    fill(0, 0);
    for (int kt = 0; kt < NK; kt++) {
        int st = kt & 1;
        if (kt + 1 < NK) {
            fill(kt + 1, st ^ 1);
            asm volatile("cp.async.wait_group 1;" ::: "memory");
        } else {
            asm volatile("cp.async.wait_group 0;" ::: "memory");
        }
        __syncthreads();
        const float* As = gsm + st * GSTG;
        const float* Bs = As + 128 * PK;
        #pragma unroll
        for (int ks = 0; ks < 4; ks++) {
            int k0 = ks * 8;
            uint32_t a[4][4], b[NSUB][2];
            #pragma unroll
            for (int mt = 0; mt < 4; mt++) {
                int r = wm + mt * 16 + g;
                float2 a0 = *(const float2*)(As + r * PK + k0 + 2 * t4);
                float2 a1 = *(const float2*)(As + (r + 8) * PK + k0 + 2 * t4);
                a[mt][0] = __float_as_uint(a0.x);
                a[mt][1] = __float_as_uint(a1.x);
                a[mt][2] = __float_as_uint(a0.y);
                a[mt][3] = __float_as_uint(a1.y);
            }
            #pragma unroll
            for (int nt = 0; nt < NSUB; nt++) {
                int n = wn + nt * 8 + g;
                float2 bv = *(const float2*)(Bs + n * PK + k0 + 2 * t4);
                b[nt][0] = __float_as_uint(bv.x);
                b[nt][1] = __float_as_uint(bv.y);
            }
            #pragma unroll
            for (int mt = 0; mt < 4; mt++)
                #pragma unroll
                for (int nt = 0; nt < NSUB; nt++)
                    mma_tf32(acc[mt][nt], a[mt], b[nt]);
        }
        __syncthreads();
    }

    if (qk) {
        if (n0 >= 1024) {
            // ---- V: pack bf16 token-pairs transposed into g_vt (cp-pair perm) ----
            bool geven = (g & 1) == 0;
            #pragma unroll
            for (int mt = 0; mt < 4; mt++) {
                int ra = m0 + wm + mt * 16 + g;
                int b_ = ra >> 10, c_ = ra & 1023;
                #pragma unroll
                for (int nt = 0; nt < NSUB; nt++) {
                    int np = n0 - 1024 + wn + nt * 8 + t4 * 2;
                    int h_ = np >> 6, e0 = np & 63;
                    int z_ = h_ * 4 + b_;
                    float v0 = acc[mt][nt][0], v1 = acc[mt][nt][1];
                    float v2 = acc[mt][nt][2], v3 = acc[mt][nt][3];
                    float e0x = __shfl_xor_sync(0xffffffffu, v0, 4);
                    float e1x = __shfl_xor_sync(0xffffffffu, v1, 4);
                    float e2x = __shfl_xor_sync(0xffffffffu, v2, 4);
                    float e3x = __shfl_xor_sync(0xffffffffu, v3, 4);
                    size_t ebase = ((size_t)z_ * 64 + e0) * 512;
                    if (geven) {
                        int cp = c_ >> 1;
                        int cps = (cp & ~7) | perm3(cp & 7);
                        vt[ebase + cps]       = pack_bf16(v0, e0x);
                        vt[ebase + 512 + cps] = pack_bf16(v1, e1x);
                    } else {
                        int cp = (c_ + 7) >> 1;
                        int cps = (cp & ~7) | perm3(cp & 7);
                        vt[ebase + cps]       = pack_bf16(e2x, v2);
                        vt[ebase + 512 + cps] = pack_bf16(e3x, v3);
                    }
                }
            }
        } else {
            // ---- Q/K: pack fp16 e-pairs (pair-permuted) into g_qk ----
            #pragma unroll
            for (int mt = 0; mt < 4; mt++) {
                int r = m0 + wm + mt * 16 + g;
                #pragma unroll
                for (int nt = 0; nt < NSUB; nt++) {
                    int c = n0 + wn + nt * 8 + t4 * 2;
                    int isK = c >= 512;
                    int cl = c & 511;
                    int h_ = cl >> 6, e = cl & 63;
                    int p = e >> 1;
                    int word = h_ * 64 + isK * 32 + ((p & ~7) | perm3(p & 7));
                    qk[(size_t)r * 512 + word] =
                        pack_f16(acc[mt][nt][0], acc[mt][nt][1]);
                    qk[(size_t)(r + 8) * 512 + word] =
                        pack_f16(acc[mt][nt][2], acc[mt][nt][3]);
                }
            }
        }
        return;
    }

    #pragma unroll
    for (int mt = 0; mt < 4; mt++) {
        #pragma unroll
        for (int nt = 0; nt < NSUB; nt++) {
            int r = m0 + wm + mt * 16 + g;
            int c = n0 + wn + nt * 8 + t4 * 2;
            float v0 = acc[mt][nt][0], v1 = acc[mt][nt][1];
            float v2 = acc[mt][nt][2], v3 = acc[mt][nt][3];
            size_t o0 = (size_t)r * ldc + c;
            size_t o1 = (size_t)(r + 8) * ldc + c;
            if (res) {
                float2 r0 = *(const float2*)(res + o0);
                float2 r1 = *(const float2*)(res + o1);
                v0 += r0.x; v1 += r0.y; v2 += r1.x; v3 += r1.y;
            }
            if (round_out) {
                v0 = rna_tf32(v0); v1 = rna_tf32(v1);
                v2 = rna_tf32(v2); v3 = rna_tf32(v3);
            }
            *(float2*)(C + o0) = make_float2(v0, v1);
            *(float2*)(C + o1) = make_float2(v2, v3);
        }
    }
}

// ---------------- fused flash attention: fp16 QK^T, bf16 PV, bitmask, 2-stage ----------------
#define KW   40                                  // K/V smem row stride in words (≡8 mod 32)
#define FSTG_W (64 * KW * 2)                     // words per stage (K + V)
#define FSTG_B (FSTG_W * 4)                      // 20480 bytes per stage
__global__ __launch_bounds__(256, 2) void flash_kernel(const float* __restrict__ Bb) {
    extern __shared__ uint32_t smu[];
    int z = blockIdx.z;
    int h = z >> 2, b = z & 3;
    int q0 = blockIdx.x * 128;
    int tid = threadIdx.x, lane = tid & 31, warp = tid >> 5;
    int g = lane >> 2, t4 = lane & 3;

    size_t rowbase = (size_t)b * THW;
    uint32_t smbase = smem_u32(smu);

    // loop-invariant fp16 Q fragments (4 k-blocks of 16)
    uint32_t qa[4][4];
    {
        const uint32_t* Q0 = g_qk + (rowbase + q0 + warp * 16 + g) * 512 + h * 64;
        const uint32_t* Q1 = Q0 + 8 * 512;
        #pragma unroll
        for (int kb = 0; kb < 4; kb++) {
            uint2 f0 = *(const uint2*)(Q0 + kb * 8 + 2 * t4);
            uint2 f1 = *(const uint2*)(Q1 + kb * 8 + 2 * t4);
            qa[kb][0] = f0.x;
            qa[kb][1] = f1.x;
            qa[kb][2] = f0.y;
            qa[kb][3] = f1.y;
        }
    }

    float oacc[8][4] = {};
    float rs0 = 0.f, rs1 = 0.f;
    const float* Bz = Bb + (size_t)z * THW * THW;
    int qr0 = q0 + warp * 16 + g;
    int qr1 = qr0 + 8;
    const uint32_t* mrow0 = g_mb + (size_t)qr0 * 32;
    const uint32_t* mrow1 = g_mb + (size_t)qr1 * 32;

    auto fill = [&](int it, int s) {
        int c0 = it * 64;
        uint32_t kb_ = smbase + s * FSTG_B;
        uint32_t vb_ = kb_ + 64 * KW * 4;
        #pragma unroll
        for (int i = 0; i < 2; i++) {
            int c = tid + i * 256;          // 0..511: K 16B chunks (64 rows x 8)
            int r = c >> 3, cc = c & 7;
            cp16(kb_ + (uint32_t)(r * KW + cc * 4) * 4,
                 g_qk + (rowbase + c0 + r) * 512 + h * 64 + 32 + cc * 4);
        }
        #pragma unroll
        for (int i = 0; i < 2; i++) {
            int c = tid + i * 256;          // 0..511: V 16B chunks (64 e x 8)
            int e = c >> 3, jj = c & 7;
            cp16(vb_ + (uint32_t)(e * KW + jj * 4) * 4,
                 &g_vt[((size_t)(z * 64) + e) * 512 + (c0 >> 1) + jj * 4]);
        }
        cp_commit();
    };

    fill(0, 0);
    for (int it = 0; it < 16; it++) {
        int st = it & 1;
        int c0 = it * 64;

        // mask words + j=0 bias prefetch while cp.async in flight
        uint2 mw0 = *(const uint2*)(mrow0 + (c0 >> 5));
        uint2 mw1 = *(const uint2*)(mrow1 + (c0 >> 5));
        size_t bo0 = (size_t)qr0 * THW + c0 + 2 * t4;
        size_t bo1 = (size_t)qr1 * THW + c0 + 2 * t4;
        float2 nbA0 = *(const float2*)(Bz + bo0);
        float2 nbA1 = *(const float2*)(Bz + bo1);
        float2 nbB0 = *(const float2*)(Bz + bo0 + 8);
        float2 nbB1 = *(const float2*)(Bz + bo1 + 8);

        if (it < 15) {
            fill(it + 1, st ^ 1);
            asm volatile("cp.async.wait_group 1;" ::: "memory");
        } else {
            asm volatile("cp.async.wait_group 0;" ::: "memory");
        }
        __syncthreads();
        const uint32_t* Ks = smu + st * FSTG_W;
        const uint32_t* Vst = Ks + 64 * KW;

        #pragma unroll
        for (int j = 0; j < 4; j++) {
            float2 bA0 = nbA0, bA1 = nbA1, bB0 = nbB0, bB1 = nbB1;
            if (j < 3) {
                size_t po = (j + 1) * 16;
                nbA0 = *(const float2*)(Bz + bo0 + po);
                nbA1 = *(const float2*)(Bz + bo1 + po);
                nbB0 = *(const float2*)(Bz + bo0 + po + 8);
                nbB1 = *(const float2*)(Bz + bo1 + po + 8);
            }

            // S tiles: fp16 m16n8k16, 4 k-blocks
            float saccA[4] = {}, saccB[4] = {};
            const uint32_t* krA = Ks + (j * 16 + g) * KW;
            const uint32_t* krB = krA + 8 * KW;
            #pragma unroll
            for (int kb = 0; kb < 4; kb++) {
                uint2 fa = *(const uint2*)(krA + kb * 8 + 2 * t4);
                uint2 fb = *(const uint2*)(krB + kb * 8 + 2 * t4);
                mma_f16(saccA, qa[kb], fa.x, fa.y);
                mma_f16(saccB, qa[kb], fb.x, fb.y);
            }

            // mask bits: cols j*16 + 2t4 + {0,1,8,9}
            uint32_t w0 = (j & 2) ? mw0.y : mw0.x;
            uint32_t w1 = (j & 2) ? mw1.y : mw1.x;
            int sh = (j & 1) * 16 + 2 * t4;
            uint32_t a0m = (w0 >> sh) & 1u,       a1m = (w0 >> (sh + 1)) & 1u;
            uint32_t b0m = (w0 >> (sh + 8)) & 1u, b1m = (w0 >> (sh + 9)) & 1u;
            uint32_t c0m = (w1 >> sh) & 1u,       c1m = (w1 >> (sh + 1)) & 1u;
            uint32_t d0m = (w1 >> (sh + 8)) & 1u, d1m = (w1 >> (sh + 9)) & 1u;

            float pA0 = a0m ? 0.f : __expf(fmaf(saccA[0], 0.125f, bA0.x));
            float pA1 = a1m ? 0.f : __expf(fmaf(saccA[1], 0.125f, bA0.y));
            float pA2 = c0m ? 0.f : __expf(fmaf(saccA[2], 0.125f, bA1.x));
            float pA3 = c1m ? 0.f : __expf(fmaf(saccA[3], 0.125f, bA1.y));
            float pB0 = b0m ? 0.f : __expf(fmaf(saccB[0], 0.125f, bB0.x));
            float pB1 = b1m ? 0.f : __expf(fmaf(saccB[1], 0.125f, bB0.y));
            float pB2 = d0m ? 0.f : __expf(fmaf(saccB[2], 0.125f, bB1.x));
            float pB3 = d1m ? 0.f : __expf(fmaf(saccB[3], 0.125f, bB1.y));
            rs0 += pA0 + pA1 + pB0 + pB1;
            rs1 += pA2 + pA3 + pB2 + pB3;

            uint32_t pa[4];
            pa[0] = pack_bf16(pA0, pA1);
            pa[1] = pack_bf16(pA2, pA3);
            pa[2] = pack_bf16(pB0, pB1);
            pa[3] = pack_bf16(pB2, pB3);

            #pragma unroll
            for (int ne = 0; ne < 8; ne++) {
                uint2 bv = *(const uint2*)(Vst + (ne * 8 + g) * KW + j * 8 + 2 * t4);
                mma_bf16(oacc[ne], pa, bv.x, bv.y);
            }
        }
        __syncthreads();
    }

    rs0 += __shfl_xor_sync(0xffffffffu, rs0, 1);
    rs0 += __shfl_xor_sync(0xffffffffu, rs0, 2);
    rs1 += __shfl_xor_sync(0xffffffffu, rs1, 1);
    rs1 += __shfl_xor_sync(0xffffffffu, rs1, 2);
    float inv0 = 1.0f / rs0, inv1 = 1.0f / rs1;

    // store O feature-permuted (k-dim of proj GEMM)
    size_t orow0 = (rowbase + qr0) * (size_t)DM;
    size_t orow1 = (rowbase + qr1) * (size_t)DM;
    #pragma unroll
    for (int nt = 0; nt < 8; nt++) {
        int base8 = h * 64 + nt * 8;
        int p0 = base8 + perm3(2 * t4);
        int p1 = base8 + perm3(2 * t4 + 1);
        g_o[orow0 + p0] = rna_tf32(oacc[nt][0] * inv0);
        g_o[orow0 + p1] = rna_tf32(oacc[nt][1] * inv0);
        g_o[orow1 + p0] = rna_tf32(oacc[nt][2] * inv1);
        g_o[orow1 + p1] = rna_tf32(oacc[nt][3] * inv1);
    }
}

// ---------------- launch ----------------
extern "C" void kernel_launch(void* const* d_in, const int* in_sizes, int n_in,
                              void* d_out, int out_size) {
    const float* x     = (const float*)d_in[0];
    const float* Bb    = (const float*)d_in[1];
    const int*   Mm    = (const int*)  d_in[2];
    const float* gamma = (const float*)d_in[3];
    const float* beta  = (const float*)d_in[4];
    const float* wq    = (const float*)d_in[5];
    const float* wk    = (const float*)d_in[6];
    const float* wv    = (const float*)d_in[7];
    const float* wp    = (const float*)d_in[8];
    float* out = (float*)d_out;

    void *p_xn, *p_o, *p_wb, *p_wpr, *p_vt, *p_qk;
    cudaGetSymbolAddress(&p_xn,  g_xn);
    cudaGetSymbolAddress(&p_o,   g_o);
    cudaGetSymbolAddress(&p_wb,  g_wb);
    cudaGetSymbolAddress(&p_wpr, g_wpr);
    cudaGetSymbolAddress(&p_vt,  g_vt);
    cudaGetSymbolAddress(&p_qk,  g_qk);

    const int gemm4_smem = (128 + 128) * PK * 2 * 4;   // 81920
    const int gemm2_smem = (128 + 64)  * PK * 2 * 4;   // 61440
    const int flash_smem = FSTG_B * 2;                 // 40960
    cudaFuncSetAttribute(gemm_mma<4>,  cudaFuncAttributeMaxDynamicSharedMemorySize, gemm4_smem);
    cudaFuncSetAttribute(gemm_mma<2>,  cudaFuncAttributeMaxDynamicSharedMemorySize, gemm2_smem);
    cudaFuncSetAttribute(flash_kernel, cudaFuncAttributeMaxDynamicSharedMemorySize, flash_smem);

    ln_kernel<<<TR, 256>>>(x, gamma, beta);
    prep_w<<<4096, 256>>>(wq, wk, wv, wp);
    prep_mask<<<4096, 256>>>(Mm);
    gemm_mma<4><<<dim3(TR / 128, 1536 / 128), 256, gemm4_smem>>>(
        (const float*)p_xn, (const float*)p_wb, nullptr, nullptr,
        (uint32_t*)p_qk, (uint32_t*)p_vt, 512, 1536, 0);
    flash_kernel<<<dim3(THW / 128, 1, NH * BS), 256, flash_smem>>>(Bb);
    gemm_mma<2><<<dim3(TR / 128, DM / 64), 256, gemm2_smem>>>(
        (const float*)p_o, (const float*)p_wpr, out, x, nullptr, nullptr, 512, DM, 0);
}

// round 9
// speedup vs baseline: 5.4094x; 1.2286x over previous
#include <cuda_runtime.h>
#include <cstdint>

#define THW 1024
#define DM  512
#define NH  8
#define DH  64
#define BS  4
#define TR  (BS*THW)       // 4096
#define LNEPS 1e-5f

// within-8-group permutation making MMA frag word pairs (t4, t4+4) adjacent
__host__ __device__ __forceinline__ int perm3(int r) { return (r < 4) ? 2 * r : 2 * r - 7; }

// ---------------- scratch ----------------
__device__ uint32_t g_xnh[(size_t)TR * 256];       // LN out fp16x2, pair-permuted words
__device__ uint32_t g_qk [(size_t)TR * 512];       // fp16x2 Q|K: [row][h*64 + (k?32:0) + word]
__device__ uint32_t g_oh [(size_t)TR * 256];       // attn out fp16x2, pair-permuted words
__device__ uint32_t g_wbh[1536 * 256];             // QKV B fp16x2 [n][word]
__device__ uint32_t g_wph[512 * 256];              // wp fp16x2 [n][word]
__device__ uint32_t g_vt [(size_t)32 * 64 * 512];  // bf16x2 V^T [z][e][cp], cp-pair-permuted
__device__ uint32_t g_mb [1024 * 32];              // M bit-packed

// ---------------- helpers ----------------
__device__ __forceinline__ uint32_t pack_bf16(float lo, float hi) {
    uint32_t r;
    asm("cvt.rn.bf16x2.f32 %0, %1, %2;" : "=r"(r) : "f"(hi), "f"(lo));
    return r;
}
__device__ __forceinline__ uint32_t pack_f16(float lo, float hi) {
    uint32_t r;
    asm("cvt.rn.f16x2.f32 %0, %1, %2;" : "=r"(r) : "f"(hi), "f"(lo));
    return r;
}
__device__ __forceinline__ uint32_t smem_u32(const void* p) {
    uint32_t a;
    asm("{ .reg .u64 t; cvta.to.shared.u64 t, %1; cvt.u32.u64 %0, t; }" : "=r"(a) : "l"(p));
    return a;
}
__device__ __forceinline__ void cp16(uint32_t dst, const void* src) {
    asm volatile("cp.async.cg.shared.global [%0], [%1], 16;" :: "r"(dst), "l"(src));
}
__device__ __forceinline__ void cp_commit() { asm volatile("cp.async.commit_group;"); }

__device__ __forceinline__ void mma_f16(float d[4], const uint32_t a[4], uint32_t b0, uint32_t b1) {
    asm volatile(
        "mma.sync.aligned.m16n8k16.row.col.f32.f16.f16.f32 "
        "{%0,%1,%2,%3}, {%4,%5,%6,%7}, {%8,%9}, {%0,%1,%2,%3};"
        : "+f"(d[0]), "+f"(d[1]), "+f"(d[2]), "+f"(d[3])
        : "r"(a[0]), "r"(a[1]), "r"(a[2]), "r"(a[3]), "r"(b0), "r"(b1));
}
__device__ __forceinline__ void mma_bf16(float d[4], const uint32_t a[4], uint32_t b0, uint32_t b1) {
    asm volatile(
        "mma.sync.aligned.m16n8k16.row.col.f32.bf16.bf16.f32 "
        "{%0,%1,%2,%3}, {%4,%5,%6,%7}, {%8,%9}, {%0,%1,%2,%3};"
        : "+f"(d[0]), "+f"(d[1]), "+f"(d[2]), "+f"(d[3])
        : "r"(a[0]), "r"(a[1]), "r"(a[2]), "r"(a[3]), "r"(b0), "r"(b1));
}

// ---------------- LayerNorm -> fp16x2 pair-permuted words ----------------
__global__ void ln_kernel(const float* __restrict__ x,
                          const float* __restrict__ gamma,
                          const float* __restrict__ beta) {
    int row = blockIdx.x;
    int t = threadIdx.x;                       // 256 threads, features (2t, 2t+1)
    float2 v = ((const float2*)(x + (size_t)row * DM))[t];

    __shared__ float red[8];
    float s = v.x + v.y;
    #pragma unroll
    for (int o = 16; o; o >>= 1) s += __shfl_xor_sync(0xffffffffu, s, o);
    if ((t & 31) == 0) red[t >> 5] = s;
    __syncthreads();
    if (t < 8) {
        float m = red[t];
        #pragma unroll
        for (int o = 4; o; o >>= 1) m += __shfl_xor_sync(0xffu, m, o);
        if (t == 0) red[0] = m;
    }
    __syncthreads();
    float mu = red[0] * (1.0f / DM);
    __syncthreads();

    float d0 = v.x - mu, d1 = v.y - mu;
    float s2 = d0 * d0 + d1 * d1;
    #pragma unroll
    for (int o = 16; o; o >>= 1) s2 += __shfl_xor_sync(0xffffffffu, s2, o);
    if ((t & 31) == 0) red[t >> 5] = s2;
    __syncthreads();
    if (t < 8) {
        float m = red[t];
        #pragma unroll
        for (int o = 4; o; o >>= 1) m += __shfl_xor_sync(0xffu, m, o);
        if (t == 0) red[0] = m;
    }
    __syncthreads();
    float rstd = rsqrtf(red[0] * (1.0f / DM) + LNEPS);

    float2 gm = ((const float2*)gamma)[t];
    float2 bt = ((const float2*)beta)[t];
    float n0 = d0 * rstd * gm.x + bt.x;
    float n1 = d1 * rstd * gm.y + bt.y;
    int wp = (t & ~7) | perm3(t & 7);
    g_xnh[(size_t)row * 256 + wp] = pack_f16(n0, n1);
}

// ---------------- prep: weights -> fp16x2 pair-permuted; mask bitpack ----------------
__global__ void prep_w(const float* __restrict__ wq, const float* __restrict__ wk,
                       const float* __restrict__ wv, const float* __restrict__ wp) {
    size_t idx = (size_t)blockIdx.x * 256 + threadIdx.x;   // (1536+512)*256 total
    if (idx < (size_t)1536 * 256) {
        int n = (int)(idx >> 8), u = (int)(idx & 255);     // u = unpermuted k-pair
        int sel = n >> 9;
        int he = n & 511;
        int h = he >> 6, e = he & 63;
        const float* w = sel == 0 ? wq : sel == 1 ? wk : wv;
        float v0 = w[((size_t)h * 512 + 2 * u) * 64 + e];
        float v1 = w[((size_t)h * 512 + 2 * u + 1) * 64 + e];
        int wpp = (u & ~7) | perm3(u & 7);
        g_wbh[(size_t)n * 256 + wpp] = pack_f16(v0, v1);
    } else {
        size_t i2 = idx - (size_t)1536 * 256;
        int n = (int)(i2 >> 8), u = (int)(i2 & 255);
        float v0 = wp[(size_t)n * 512 + 2 * u];
        float v1 = wp[(size_t)n * 512 + 2 * u + 1];
        int wpp = (u & ~7) | perm3(u & 7);
        g_wph[(size_t)n * 256 + wpp] = pack_f16(v0, v1);
    }
}

__global__ void prep_mask(const int* __restrict__ M) {
    int idx = blockIdx.x * 256 + threadIdx.x;
    bool m = M[idx] != 0;
    uint32_t w = __ballot_sync(0xffffffffu, m);
    if ((idx & 31) == 0) g_mb[idx >> 5] = w;
}

// ---------------- fp16 MMA GEMM, 2-stage cp.async, LDS.64 fragments ----------------
// A: [M][256] fp16x2 words (pair-permuted). B: [N][256] same. k-tile = 16 words (32 k).
// qk/vt non-null => QKV mode epilogue. res non-null => +residual into C (fp32).
#define PKW 24
template <int NSUB>
__global__ __launch_bounds__(256) void gemm_h(const uint32_t* __restrict__ A,
                                              const uint32_t* __restrict__ Bw,
                                              float* __restrict__ C,
                                              const float* __restrict__ res,
                                              uint32_t* __restrict__ qk,
                                              uint32_t* __restrict__ vt,
                                              int ldc) {
    constexpr int NBLK = NSUB * 32;
    constexpr int GSTG = (128 + NBLK) * PKW;   // uint32 words per stage
    extern __shared__ uint32_t gsmh[];
    int tid = threadIdx.x, lane = tid & 31, warp = tid >> 5;
    int wm = (warp >> 2) * 64;
    int wn = (warp & 3) * NSUB * 8;
    int m0 = blockIdx.x * 128, n0 = blockIdx.y * NBLK;
    int g = lane >> 2, t4 = lane & 3;

    float acc[4][NSUB][4] = {};

    auto fill = [&](int kt, int s) {
        uint32_t ab = smem_u32(gsmh + s * GSTG);
        uint32_t bb = ab + 128 * PKW * 4;
        #pragma unroll
        for (int i = 0; i < 2; i++) {
            int c = tid + i * 256;            // 512 chunks: 128 rows x 4
            int r = c >> 2, cc = c & 3;
            cp16(ab + (uint32_t)(r * PKW + cc * 4) * 4,
                 A + (size_t)(m0 + r) * 256 + kt * 16 + cc * 4);
        }
        #pragma unroll
        for (int i = 0; i < NSUB / 2; i++) {
            int c = tid + i * 256;            // NBLK*4 chunks
            int r = c >> 2, cc = c & 3;
            cp16(bb + (uint32_t)(r * PKW + cc * 4) * 4,
                 Bw + (size_t)(n0 + r) * 256 + kt * 16 + cc * 4);
        }
        cp_commit();
    };

    fill(0, 0);
    for (int kt = 0; kt < 16; kt++) {
        int st = kt & 1;
        if (kt + 1 < 16) {
            fill(kt + 1, st ^ 1);
            asm volatile("cp.async.wait_group 1;" ::: "memory");
        } else {
            asm volatile("cp.async.wait_group 0;" ::: "memory");
        }
        __syncthreads();
        const uint32_t* As = gsmh + st * GSTG;
        const uint32_t* Bs = As + 128 * PKW;
        #pragma unroll
        for (int kb = 0; kb < 2; kb++) {
            uint32_t a[4][4], b[NSUB][2];
            #pragma unroll
            for (int mt = 0; mt < 4; mt++) {
                int r = wm + mt * 16 + g;
                uint2 f0 = *(const uint2*)(As + r * PKW + kb * 8 + 2 * t4);
                uint2 f1 = *(const uint2*)(As + (r + 8) * PKW + kb * 8 + 2 * t4);
                a[mt][0] = f0.x;
                a[mt][1] = f1.x;
                a[mt][2] = f0.y;
                a[mt][3] = f1.y;
            }
            #pragma unroll
            for (int nt = 0; nt < NSUB; nt++) {
                int n = wn + nt * 8 + g;
                uint2 bv = *(const uint2*)(Bs + n * PKW + kb * 8 + 2 * t4);
                b[nt][0] = bv.x;
                b[nt][1] = bv.y;
            }
            #pragma unroll
            for (int mt = 0; mt < 4; mt++)
                #pragma unroll
                for (int nt = 0; nt < NSUB; nt++)
                    mma_f16(acc[mt][nt], a[mt], b[nt][0], b[nt][1]);
        }
        __syncthreads();
    }

    if (qk) {
        if (n0 >= 1024) {
            // ---- V: pack bf16 token-pairs transposed into g_vt (cp-pair perm) ----
            bool geven = (g & 1) == 0;
            #pragma unroll
            for (int mt = 0; mt < 4; mt++) {
                int ra = m0 + wm + mt * 16 + g;
                int b_ = ra >> 10, c_ = ra & 1023;
                #pragma unroll
                for (int nt = 0; nt < NSUB; nt++) {
                    int np = n0 - 1024 + wn + nt * 8 + t4 * 2;
                    int h_ = np >> 6, e0 = np & 63;
                    int z_ = h_ * 4 + b_;
                    float v0 = acc[mt][nt][0], v1 = acc[mt][nt][1];
                    float v2 = acc[mt][nt][2], v3 = acc[mt][nt][3];
                    float e0x = __shfl_xor_sync(0xffffffffu, v0, 4);
                    float e1x = __shfl_xor_sync(0xffffffffu, v1, 4);
                    float e2x = __shfl_xor_sync(0xffffffffu, v2, 4);
                    float e3x = __shfl_xor_sync(0xffffffffu, v3, 4);
                    size_t ebase = ((size_t)z_ * 64 + e0) * 512;
                    if (geven) {
                        int cp = c_ >> 1;
                        int cps = (cp & ~7) | perm3(cp & 7);
                        vt[ebase + cps]       = pack_bf16(v0, e0x);
                        vt[ebase + 512 + cps] = pack_bf16(v1, e1x);
                    } else {
                        int cp = (c_ + 7) >> 1;
                        int cps = (cp & ~7) | perm3(cp & 7);
                        vt[ebase + cps]       = pack_bf16(e2x, v2);
                        vt[ebase + 512 + cps] = pack_bf16(e3x, v3);
                    }
                }
            }
        } else {
            // ---- Q/K: pack fp16 e-pairs (pair-permuted) into g_qk ----
            #pragma unroll
            for (int mt = 0; mt < 4; mt++) {
                int r = m0 + wm + mt * 16 + g;
                #pragma unroll
                for (int nt = 0; nt < NSUB; nt++) {
                    int c = n0 + wn + nt * 8 + t4 * 2;
                    int isK = c >= 512;
                    int cl = c & 511;
                    int h_ = cl >> 6, e = cl & 63;
                    int p = e >> 1;
                    int word = h_ * 64 + isK * 32 + ((p & ~7) | perm3(p & 7));
                    qk[(size_t)r * 512 + word] =
                        pack_f16(acc[mt][nt][0], acc[mt][nt][1]);
                    qk[(size_t)(r + 8) * 512 + word] =
                        pack_f16(acc[mt][nt][2], acc[mt][nt][3]);
                }
            }
        }
        return;
    }

    // ---- plain C epilogue (+res) ----
    #pragma unroll
    for (int mt = 0; mt < 4; mt++) {
        #pragma unroll
        for (int nt = 0; nt < NSUB; nt++) {
            int r = m0 + wm + mt * 16 + g;
            int c = n0 + wn + nt * 8 + t4 * 2;
            float v0 = acc[mt][nt][0], v1 = acc[mt][nt][1];
            float v2 = acc[mt][nt][2], v3 = acc[mt][nt][3];
            size_t o0 = (size_t)r * ldc + c;
            size_t o1 = (size_t)(r + 8) * ldc + c;
            if (res) {
                float2 r0 = *(const float2*)(res + o0);
                float2 r1 = *(const float2*)(res + o1);
                v0 += r0.x; v1 += r0.y; v2 += r1.x; v3 += r1.y;
            }
            *(float2*)(C + o0) = make_float2(v0, v1);
            *(float2*)(C + o1) = make_float2(v2, v3);
        }
    }
}

// ---------------- fused flash attention: fp16 QK^T, bf16 PV, bitmask, 2-stage ----------------
#define KW   40
#define FSTG_W (64 * KW * 2)
#define FSTG_B (FSTG_W * 4)                      // 20480 bytes per stage
__global__ __launch_bounds__(256, 2) void flash_kernel(const float* __restrict__ Bb) {
    extern __shared__ uint32_t smu[];
    int z = blockIdx.z;
    int h = z >> 2, b = z & 3;
    int q0 = blockIdx.x * 128;
    int tid = threadIdx.x, lane = tid & 31, warp = tid >> 5;
    int g = lane >> 2, t4 = lane & 3;

    size_t rowbase = (size_t)b * THW;
    uint32_t smbase = smem_u32(smu);

    uint32_t qa[4][4];
    {
        const uint32_t* Q0 = g_qk + (rowbase + q0 + warp * 16 + g) * 512 + h * 64;
        const uint32_t* Q1 = Q0 + 8 * 512;
        #pragma unroll
        for (int kb = 0; kb < 4; kb++) {
            uint2 f0 = *(const uint2*)(Q0 + kb * 8 + 2 * t4);
            uint2 f1 = *(const uint2*)(Q1 + kb * 8 + 2 * t4);
            qa[kb][0] = f0.x;
            qa[kb][1] = f1.x;
            qa[kb][2] = f0.y;
            qa[kb][3] = f1.y;
        }
    }

    float oacc[8][4] = {};
    float rs0 = 0.f, rs1 = 0.f;
    const float* Bz = Bb + (size_t)z * THW * THW;
    int qr0 = q0 + warp * 16 + g;
    int qr1 = qr0 + 8;
    const uint32_t* mrow0 = g_mb + (size_t)qr0 * 32;
    const uint32_t* mrow1 = g_mb + (size_t)qr1 * 32;

    auto fill = [&](int it, int s) {
        int c0 = it * 64;
        uint32_t kb_ = smbase + s * FSTG_B;
        uint32_t vb_ = kb_ + 64 * KW * 4;
        #pragma unroll
        for (int i = 0; i < 2; i++) {
            int c = tid + i * 256;
            int r = c >> 3, cc = c & 7;
            cp16(kb_ + (uint32_t)(r * KW + cc * 4) * 4,
                 g_qk + (rowbase + c0 + r) * 512 + h * 64 + 32 + cc * 4);
        }
        #pragma unroll
        for (int i = 0; i < 2; i++) {
            int c = tid + i * 256;
            int e = c >> 3, jj = c & 7;
            cp16(vb_ + (uint32_t)(e * KW + jj * 4) * 4,
                 &g_vt[((size_t)(z * 64) + e) * 512 + (c0 >> 1) + jj * 4]);
        }
        cp_commit();
    };

    fill(0, 0);
    for (int it = 0; it < 16; it++) {
        int st = it & 1;
        int c0 = it * 64;

        uint2 mw0 = *(const uint2*)(mrow0 + (c0 >> 5));
        uint2 mw1 = *(const uint2*)(mrow1 + (c0 >> 5));
        size_t bo0 = (size_t)qr0 * THW + c0 + 2 * t4;
        size_t bo1 = (size_t)qr1 * THW + c0 + 2 * t4;
        float2 nbA0 = *(const float2*)(Bz + bo0);
        float2 nbA1 = *(const float2*)(Bz + bo1);
        float2 nbB0 = *(const float2*)(Bz + bo0 + 8);
        float2 nbB1 = *(const float2*)(Bz + bo1 + 8);

        if (it < 15) {
            fill(it + 1, st ^ 1);
            asm volatile("cp.async.wait_group 1;" ::: "memory");
        } else {
            asm volatile("cp.async.wait_group 0;" ::: "memory");
        }
        __syncthreads();
        const uint32_t* Ks = smu + st * FSTG_W;
        const uint32_t* Vst = Ks + 64 * KW;

        #pragma unroll
        for (int j = 0; j < 4; j++) {
            float2 bA0 = nbA0, bA1 = nbA1, bB0 = nbB0, bB1 = nbB1;
            if (j < 3) {
                size_t po = (j + 1) * 16;
                nbA0 = *(const float2*)(Bz + bo0 + po);
                nbA1 = *(const float2*)(Bz + bo1 + po);
                nbB0 = *(const float2*)(Bz + bo0 + po + 8);
                nbB1 = *(const float2*)(Bz + bo1 + po + 8);
            }

            float saccA[4] = {}, saccB[4] = {};
            const uint32_t* krA = Ks + (j * 16 + g) * KW;
            const uint32_t* krB = krA + 8 * KW;
            #pragma unroll
            for (int kb = 0; kb < 4; kb++) {
                uint2 fa = *(const uint2*)(krA + kb * 8 + 2 * t4);
                uint2 fb = *(const uint2*)(krB + kb * 8 + 2 * t4);
                mma_f16(saccA, qa[kb], fa.x, fa.y);
                mma_f16(saccB, qa[kb], fb.x, fb.y);
            }

            uint32_t w0 = (j & 2) ? mw0.y : mw0.x;
            uint32_t w1 = (j & 2) ? mw1.y : mw1.x;
            int sh = (j & 1) * 16 + 2 * t4;
            uint32_t a0m = (w0 >> sh) & 1u,       a1m = (w0 >> (sh + 1)) & 1u;
            uint32_t b0m = (w0 >> (sh + 8)) & 1u, b1m = (w0 >> (sh + 9)) & 1u;
            uint32_t c0m = (w1 >> sh) & 1u,       c1m = (w1 >> (sh + 1)) & 1u;
            uint32_t d0m = (w1 >> (sh + 8)) & 1u, d1m = (w1 >> (sh + 9)) & 1u;

            float pA0 = a0m ? 0.f : __expf(fmaf(saccA[0], 0.125f, bA0.x));
            float pA1 = a1m ? 0.f : __expf(fmaf(saccA[1], 0.125f, bA0.y));
            float pA2 = c0m ? 0.f : __expf(fmaf(saccA[2], 0.125f, bA1.x));
            float pA3 = c1m ? 0.f : __expf(fmaf(saccA[3], 0.125f, bA1.y));
            float pB0 = b0m ? 0.f : __expf(fmaf(saccB[0], 0.125f, bB0.x));
            float pB1 = b1m ? 0.f : __expf(fmaf(saccB[1], 0.125f, bB0.y));
            float pB2 = d0m ? 0.f : __expf(fmaf(saccB[2], 0.125f, bB1.x));
            float pB3 = d1m ? 0.f : __expf(fmaf(saccB[3], 0.125f, bB1.y));
            rs0 += pA0 + pA1 + pB0 + pB1;
            rs1 += pA2 + pA3 + pB2 + pB3;

            uint32_t pa[4];
            pa[0] = pack_bf16(pA0, pA1);
            pa[1] = pack_bf16(pA2, pA3);
            pa[2] = pack_bf16(pB0, pB1);
            pa[3] = pack_bf16(pB2, pB3);

            #pragma unroll
            for (int ne = 0; ne < 8; ne++) {
                uint2 bv = *(const uint2*)(Vst + (ne * 8 + g) * KW + j * 8 + 2 * t4);
                mma_bf16(oacc[ne], pa, bv.x, bv.y);
            }
        }
        __syncthreads();
    }

    rs0 += __shfl_xor_sync(0xffffffffu, rs0, 1);
    rs0 += __shfl_xor_sync(0xffffffffu, rs0, 2);
    rs1 += __shfl_xor_sync(0xffffffffu, rs1, 1);
    rs1 += __shfl_xor_sync(0xffffffffu, rs1, 2);
    float inv0 = 1.0f / rs0, inv1 = 1.0f / rs1;

    // store O as fp16x2 pair-permuted words (A operand of proj GEMM)
    size_t orow0 = (rowbase + qr0) * (size_t)256;
    size_t orow1 = (rowbase + qr1) * (size_t)256;
    #pragma unroll
    for (int nt = 0; nt < 8; nt++) {
        int wi = h * 32 + nt * 4 + t4;
        int wpp = (wi & ~7) | perm3(wi & 7);
        g_oh[orow0 + wpp] = pack_f16(oacc[nt][0] * inv0, oacc[nt][1] * inv0);
        g_oh[orow1 + wpp] = pack_f16(oacc[nt][2] * inv1, oacc[nt][3] * inv1);
    }
}

// ---------------- launch ----------------
extern "C" void kernel_launch(void* const* d_in, const int* in_sizes, int n_in,
                              void* d_out, int out_size) {
    const float* x     = (const float*)d_in[0];
    const float* Bb    = (const float*)d_in[1];
    const int*   Mm    = (const int*)  d_in[2];
    const float* gamma = (const float*)d_in[3];
    const float* beta  = (const float*)d_in[4];
    const float* wq    = (const float*)d_in[5];
    const float* wk    = (const float*)d_in[6];
    const float* wv    = (const float*)d_in[7];
    const float* wp    = (const float*)d_in[8];
    float* out = (float*)d_out;

    void *p_xnh, *p_oh, *p_wbh, *p_wph, *p_vt, *p_qk;
    cudaGetSymbolAddress(&p_xnh, g_xnh);
    cudaGetSymbolAddress(&p_oh,  g_oh);
    cudaGetSymbolAddress(&p_wbh, g_wbh);
    cudaGetSymbolAddress(&p_wph, g_wph);
    cudaGetSymbolAddress(&p_vt,  g_vt);
    cudaGetSymbolAddress(&p_qk,  g_qk);

    const int gemm4_smem = (128 + 128) * PKW * 2 * 4;  // 49152
    const int gemm2_smem = (128 + 64)  * PKW * 2 * 4;  // 36864
    const int flash_smem = FSTG_B * 2;                 // 40960
    cudaFuncSetAttribute(gemm_h<4>,    cudaFuncAttributeMaxDynamicSharedMemorySize, gemm4_smem);
    cudaFuncSetAttribute(gemm_h<2>,    cudaFuncAttributeMaxDynamicSharedMemorySize, gemm2_smem);
    cudaFuncSetAttribute(flash_kernel, cudaFuncAttributeMaxDynamicSharedMemorySize, flash_smem);

    ln_kernel<<<TR, 256>>>(x, gamma, beta);
    prep_w<<<2048, 256>>>(wq, wk, wv, wp);
    prep_mask<<<4096, 256>>>(Mm);
    gemm_h<4><<<dim3(TR / 128, 1536 / 128), 256, gemm4_smem>>>(
        (const uint32_t*)p_xnh, (const uint32_t*)p_wbh, nullptr, nullptr,
        (uint32_t*)p_qk, (uint32_t*)p_vt, 1536);
    flash_kernel<<<dim3(THW / 128, 1, NH * BS), 256, flash_smem>>>(Bb);
    gemm_h<2><<<dim3(TR / 128, DM / 64), 256, gemm2_smem>>>(
        (const uint32_t*)p_oh, (const uint32_t*)p_wph, out, x,
        nullptr, nullptr, DM);
}